// round 14
// baseline (speedup 1.0000x reference)
#include <cuda_runtime.h>
#include <cuda_bf16.h>
#include <math.h>

#define L_    4
#define B_    2
#define QLEN_ 512
#define MLEN_ 512
#define CLEN_ 1024
#define RLEN_ 1536
#define H_    1024
#define NH_   16
#define D_    64
#define F_    4096
#define LN_EPS_ 1e-12f

#define EFSTRIDE ((long long)B_*NH_*QLEN_)
#define PADE 1024

typedef __nv_bfloat16 bf16;
typedef __nv_bfloat162 bf162;

__device__ float g_x  [B_*QLEN_*H_];
__device__ float g_q  [B_*QLEN_*H_];
__device__ float g_sc [(long long)B_*NH_*QLEN_*CLEN_];
__device__ float g_bd [(long long)B_*NH_*QLEN_*RLEN_];
__device__ float g_ef [2*B_*NH_*QLEN_];
__device__ float g_ao [B_*QLEN_*H_];
__device__ float g_y  [B_*QLEN_*H_];
__device__ int   g_segmode;

__device__ bf16 g_xh [B_*QLEN_*H_+PADE],  g_xl [B_*QLEN_*H_+PADE];
__device__ bf16 g_cth[B_*CLEN_*H_+PADE],  g_ctl[B_*CLEN_*H_+PADE];
__device__ bf16 g_peh[B_*RLEN_*H_+PADE],  g_pel[B_*RLEN_*H_+PADE];
__device__ bf16 g_qch[B_*QLEN_*H_+PADE],  g_qcl[B_*QLEN_*H_+PADE];
__device__ bf16 g_qph[B_*QLEN_*H_+PADE],  g_qpl[B_*QLEN_*H_+PADE];
__device__ bf16 g_kh [B_*CLEN_*H_+PADE],  g_kl [B_*CLEN_*H_+PADE];
__device__ bf16 g_vh [B_*CLEN_*H_+PADE],  g_vl [B_*CLEN_*H_+PADE];
__device__ bf16 g_rh [B_*RLEN_*H_+PADE],  g_rl [B_*RLEN_*H_+PADE];
__device__ bf16 g_ph [(long long)B_*NH_*QLEN_*CLEN_+PADE], g_pl[(long long)B_*NH_*QLEN_*CLEN_+PADE];
__device__ bf16 g_ath[B_*QLEN_*H_+PADE],  g_atl[B_*QLEN_*H_+PADE];
__device__ bf16 g_yh [B_*QLEN_*H_+PADE],  g_yl [B_*QLEN_*H_+PADE];
__device__ bf16 g_mih[B_*QLEN_*F_+PADE],  g_mil[B_*QLEN_*F_+PADE];
__device__ bf16 g_wqh[L_*H_*H_+PADE], g_wql[L_*H_*H_+PADE];
__device__ bf16 g_wkh[L_*H_*H_+PADE], g_wkl[L_*H_*H_+PADE];
__device__ bf16 g_wvh[L_*H_*H_+PADE], g_wvl[L_*H_*H_+PADE];
__device__ bf16 g_wrh[L_*H_*H_+PADE], g_wrl[L_*H_*H_+PADE];
__device__ bf16 g_woh[L_*H_*H_+PADE], g_wol[L_*H_*H_+PADE];
__device__ bf16 g_f1h[L_*H_*F_+PADE], g_f1l[L_*H_*F_+PADE];
__device__ bf16 g_f2h[L_*F_*H_+PADE], g_f2l[L_*F_*H_+PADE];

__device__ __forceinline__ void split1(float v, bf16& h, bf16& l) {
    h = __float2bfloat16(v);
    l = __float2bfloat16(v - __bfloat162float(h));
}

#define TM 128
#define ASTR32 40
#define STAGES_ 3
#define A_ST32 (128*ASTR32)

__device__ __forceinline__ unsigned smaddr(const void* p) {
    return (unsigned)__cvta_generic_to_shared(p);
}

#define CPA16(dst, src) asm volatile( \
    "cp.async.ca.shared.global [%0], [%1], 16;" :: "r"(dst), "l"(src))
#define CP_COMMIT() asm volatile("cp.async.commit_group;")
#define CP_WAIT1()  asm volatile("cp.async.wait_group 1;")

#define LDSM_X4(r, a) asm volatile( \
    "ldmatrix.sync.aligned.m8n8.x4.shared.b16 {%0,%1,%2,%3}, [%4];" \
    : "=r"((r)[0]), "=r"((r)[1]), "=r"((r)[2]), "=r"((r)[3]) : "r"(a))
#define LDSM_X2(r, a) asm volatile( \
    "ldmatrix.sync.aligned.m8n8.x2.shared.b16 {%0,%1}, [%2];" \
    : "=r"((r)[0]), "=r"((r)[1]) : "r"(a))
#define LDSM_X2T(r, a) asm volatile( \
    "ldmatrix.sync.aligned.m8n8.x2.trans.shared.b16 {%0,%1}, [%2];" \
    : "=r"((r)[0]), "=r"((r)[1]) : "r"(a))
#define MMA_BF16(c, a, b) asm volatile( \
    "mma.sync.aligned.m16n8k16.row.col.f32.bf16.bf16.f32 " \
    "{%0,%1,%2,%3}, {%4,%5,%6,%7}, {%8,%9}, {%0,%1,%2,%3};" \
    : "+f"((c)[0]), "+f"((c)[1]), "+f"((c)[2]), "+f"((c)[3]) \
    : "r"((a)[0]), "r"((a)[1]), "r"((a)[2]), "r"((a)[3]), "r"((b)[0]), "r"((b)[1]))

template<int TB, int TN_>
__device__ __forceinline__ void gemm_core(
    const bf16* __restrict__ Ah, const bf16* __restrict__ Al,
    const bf16* __restrict__ Bh, const bf16* __restrict__ Bl,
    int m0, int n0, int K, int lda, int ldb,
    float (&acc)[2][TN_/32][4])
{
    constexpr int WN   = TN_ / 4;
    constexpr int NF   = WN / 8;
    constexpr int BSTR = TN_ + 8;
    constexpr int BS   = (TB == 0) ? (32 * BSTR) : A_ST32;

    extern __shared__ __align__(16) unsigned char dsm_raw[];
    bf16* sAp = reinterpret_cast<bf16*>(dsm_raw);
    bf16* sBp = sAp + STAGES_ * 2 * A_ST32;

    const int t    = threadIdx.x;
    const int lane = t & 31;
    const int warp = t >> 5;
    const int wm = (warp & 3) * 32;
    const int wn = (warp >> 2) * WN;

#pragma unroll
    for (int mf = 0; mf < 2; mf++)
#pragma unroll
        for (int nf = 0; nf < NF; nf++)
#pragma unroll
            for (int e = 0; e < 4; e++) acc[mf][nf][e] = 0.f;

    const int ar  = t >> 2;
    const int ak8 = (t & 3) * 8;
    const int b0r = t >> 4;
    const int b0c = (t & 15) * 8;
    const int b4r = (t & 255) >> 3;
    const int b4c = (t & 7) * 8;

    auto issue = [&](int st, int k0) {
        {
            unsigned d = smaddr(sAp + (st * 2) * A_ST32 + ar * ASTR32 + ak8);
            CPA16(d, Ah + (long long)(m0 + ar) * lda + k0 + ak8);
            CPA16(d + A_ST32 * 2, Al + (long long)(m0 + ar) * lda + k0 + ak8);
        }
        if (TB == 0) {
            if (TN_ == 128) {
                unsigned d = smaddr(sBp + (st * 2) * BS + b0r * BSTR + b0c);
                CPA16(d, Bh + (long long)(k0 + b0r) * ldb + n0 + b0c);
                CPA16(d + BS * 2, Bl + (long long)(k0 + b0r) * ldb + n0 + b0c);
            } else if (t < 256) {
                unsigned d = smaddr(sBp + (st * 2) * BS + b4r * BSTR + b4c);
                CPA16(d, Bh + (long long)(k0 + b4r) * ldb + n0 + b4c);
                CPA16(d + BS * 2, Bl + (long long)(k0 + b4r) * ldb + n0 + b4c);
            }
        } else {
            unsigned d = smaddr(sBp + (st * 2) * BS + ar * ASTR32 + ak8);
            CPA16(d, Bh + (long long)(n0 + ar) * ldb + k0 + ak8);
            CPA16(d + BS * 2, Bl + (long long)(n0 + ar) * ldb + k0 + ak8);
        }
        CP_COMMIT();
    };

    auto compute = [&](int st) {
        bf16* A0 = sAp + (st * 2) * A_ST32;
        bf16* B0 = sBp + (st * 2) * BS;
#pragma unroll
        for (int p = 0; p < 2; p++) {
            unsigned aHi = smaddr(A0 + (wm + (lane & 15)) * ASTR32 + p * 16 + (lane >> 4) * 8);
            unsigned aLo = aHi + A_ST32 * 2;
            unsigned bHi = (TB == 0)
                ? smaddr(B0 + (p * 16 + (lane & 15)) * BSTR + wn)
                : smaddr(B0 + (wn + (lane & 7)) * ASTR32 + p * 16 + ((lane >> 3) & 1) * 8);
            unsigned bLo = bHi + BS * 2;

            unsigned ah[2][4], bh[NF][2], bl[NF][2];
#pragma unroll
            for (int mf = 0; mf < 2; mf++) LDSM_X4(ah[mf], aHi + mf * (16 * ASTR32 * 2));
#pragma unroll
            for (int nf = 0; nf < NF; nf++) {
                if (TB == 0) {
                    LDSM_X2T(bh[nf], bHi + nf * 16);
                    LDSM_X2T(bl[nf], bLo + nf * 16);
                } else {
                    LDSM_X2(bh[nf], bHi + nf * (8 * ASTR32 * 2));
                    LDSM_X2(bl[nf], bLo + nf * (8 * ASTR32 * 2));
                }
            }
#pragma unroll
            for (int mf = 0; mf < 2; mf++)
#pragma unroll
                for (int nf = 0; nf < NF; nf++)
                    MMA_BF16(acc[mf][nf], ah[mf], bh[nf]);
#pragma unroll
            for (int mf = 0; mf < 2; mf++)
#pragma unroll
                for (int nf = 0; nf < NF; nf++)
                    MMA_BF16(acc[mf][nf], ah[mf], bl[nf]);
#pragma unroll
            for (int mf = 0; mf < 2; mf++) LDSM_X4(ah[mf], aLo + mf * (16 * ASTR32 * 2));
#pragma unroll
            for (int mf = 0; mf < 2; mf++)
#pragma unroll
                for (int nf = 0; nf < NF; nf++)
                    MMA_BF16(acc[mf][nf], ah[mf], bh[nf]);
        }
    };

    const int kT = K / 32;
    int issued = 0;
    for (; issued < STAGES_ - 1 && issued < kT; issued++) issue(issued, issued * 32);

    for (int i = 0; i < kT; i++) {
        CP_WAIT1();
        __syncthreads();
        compute(i % STAGES_);
        if (issued < kT) { issue(issued % STAGES_, issued * 32); issued++; }
        else             { CP_COMMIT(); }
    }
}

static inline int smem_bytes(int tb, int tn) {
    int bs = (tb == 0) ? 32 * (tn + 8) : A_ST32;
    return STAGES_ * 2 * (A_ST32 + bs) * 2;
}

// ---------------- generic GEMM (pv / wo / ffn1 / ffn2) ----------------
template<int TB, int TN_>
__global__ void __launch_bounds__(512)
gemm_bf(const bf16* __restrict__ Ah, const bf16* __restrict__ Al,
        const bf16* __restrict__ Bh, const bf16* __restrict__ Bl,
        float* __restrict__ C, bf16* __restrict__ Ch, bf16* __restrict__ Cl,
        int M, int N, int K, int lda, int ldb, int ldc,
        const float* __restrict__ bias, int relu,
        int inner,
        long long oAo, long long oAi, long long oBo, long long oBi,
        long long oCo, long long oCi)
{
    constexpr int NF = TN_ / 32;

    int z  = blockIdx.z;
    int zo = z / inner;
    int zi = z - zo * inner;
    Ah += zo * oAo + zi * oAi;
    Al += zo * oAo + zi * oAi;
    Bh += zo * oBo + zi * oBi;
    Bl += zo * oBo + zi * oBi;
    long long cofs = zo * oCo + zi * oCi;
    if (C)  C  += cofs;
    if (Ch) { Ch += cofs; Cl += cofs; }

    const int m0 = blockIdx.y * TM;
    const int n0 = blockIdx.x * TN_;
    float acc[2][NF][4];
    gemm_core<TB, TN_>(Ah, Al, Bh, Bl, m0, n0, K, lda, ldb, acc);

    const int lane = threadIdx.x & 31;
    const int warp = threadIdx.x >> 5;
    const int wm = (warp & 3) * 32;
    const int wn = (warp >> 2) * (TN_ / 4);
    const int er = lane >> 2;
    const int ec = (lane & 3) * 2;
#pragma unroll
    for (int mf = 0; mf < 2; mf++) {
#pragma unroll
        for (int nf = 0; nf < NF; nf++) {
            int gm = m0 + wm + mf * 16 + er;
            int gn = n0 + wn + nf * 8 + ec;
#pragma unroll
            for (int half = 0; half < 2; half++) {
                int rm = gm + half * 8;
                if (rm >= M) continue;
                float v0 = acc[mf][nf][half * 2 + 0];
                float v1 = acc[mf][nf][half * 2 + 1];
                if (bias) { if (gn < N) v0 += bias[gn]; if (gn + 1 < N) v1 += bias[gn + 1]; }
                if (relu) { v0 = fmaxf(v0, 0.f); v1 = fmaxf(v1, 0.f); }
                if (gn < N) {
                    if (C) {
                        C[(long long)rm * ldc + gn] = v0;
                        if (gn + 1 < N) C[(long long)rm * ldc + gn + 1] = v1;
                    }
                    if (Ch && gn + 1 < N) {
                        bf16 h0, l0, h1, l1;
                        split1(v0, h0, l0); split1(v1, h1, l1);
                        bf162 hp; hp.x = h0; hp.y = h1;
                        bf162 lp; lp.x = l0; lp.y = l1;
                        *reinterpret_cast<bf162*>(&Ch[(long long)rm * ldc + gn]) = hp;
                        *reinterpret_cast<bf162*>(&Cl[(long long)rm * ldc + gn]) = lp;
                    }
                }
            }
        }
    }
}

static void launch_bf(bool transB,
                      const bf16* Ah, const bf16* Al,
                      const bf16* Bh, const bf16* Bl,
                      float* C, bf16* Ch, bf16* Cl,
                      int M, int N, int K, int lda, int ldb, int ldc,
                      const float* bias, int relu,
                      int batches, int inner,
                      long long oAo, long long oAi,
                      long long oBo, long long oBi,
                      long long oCo, long long oCi,
                      bool tn64 = false)
{
    int tn = tn64 ? 64 : 128;
    dim3 grid((N + tn - 1) / tn, (M + TM - 1) / TM, batches);
    int sm = smem_bytes(transB ? 1 : 0, tn);
    if (transB) {
        if (tn64)
            gemm_bf<1,64><<<grid, 512, sm>>>(Ah, Al, Bh, Bl, C, Ch, Cl, M, N, K, lda, ldb, ldc,
                                             bias, relu, inner, oAo, oAi, oBo, oBi, oCo, oCi);
        else
            gemm_bf<1,128><<<grid, 512, sm>>>(Ah, Al, Bh, Bl, C, Ch, Cl, M, N, K, lda, ldb, ldc,
                                              bias, relu, inner, oAo, oAi, oBo, oBi, oCo, oCi);
    } else {
        if (tn64)
            gemm_bf<0,64><<<grid, 512, sm>>>(Ah, Al, Bh, Bl, C, Ch, Cl, M, N, K, lda, ldb, ldc,
                                             bias, relu, inner, oAo, oAi, oBo, oBi, oCo, oCi);
        else
            gemm_bf<0,128><<<grid, 512, sm>>>(Ah, Al, Bh, Bl, C, Ch, Cl, M, N, K, lda, ldb, ldc,
                                              bias, relu, inner, oAo, oAi, oBo, oBi, oCo, oCi);
    }
}

// ---------------- projection megakernel: q+k+v+r, one launch per layer --------
__global__ void __launch_bounds__(512)
proj_kernel(const float* __restrict__ cb, const float* __restrict__ pb, int layer)
{
    int id = blockIdx.x;
    int seg, local;
    const bf16 *Ah, *Al, *Bh, *Bl;
    long long wofs = (long long)layer * H_ * H_;
    if (id < 64)       { seg = 0; local = id;       Ah = g_xh;  Al = g_xl;  Bh = g_wqh + wofs; Bl = g_wql + wofs; }
    else if (id < 192) { seg = 1; local = id - 64;  Ah = g_cth; Al = g_ctl; Bh = g_wkh + wofs; Bl = g_wkl + wofs; }
    else if (id < 320) { seg = 2; local = id - 192; Ah = g_cth; Al = g_ctl; Bh = g_wvh + wofs; Bl = g_wvl + wofs; }
    else               { seg = 3; local = id - 320; Ah = g_peh; Al = g_pel; Bh = g_wrh + wofs; Bl = g_wrl + wofs; }

    const int m0 = (local >> 3) * TM;
    const int n0 = (local & 7) * 128;
    float acc[2][4][4];
    gemm_core<0, 128>(Ah, Al, Bh, Bl, m0, n0, H_, H_, H_, acc);

    const int lane = threadIdx.x & 31;
    const int warp = threadIdx.x >> 5;
    const int wm = (warp & 3) * 32;
    const int wn = (warp >> 2) * 32;
    const int er = lane >> 2;
    const int ec = (lane & 3) * 2;

#pragma unroll
    for (int mf = 0; mf < 2; mf++) {
#pragma unroll
        for (int nf = 0; nf < 4; nf++) {
            int gm = m0 + wm + mf * 16 + er;
            int gn = n0 + wn + nf * 8 + ec;
#pragma unroll
            for (int half = 0; half < 2; half++) {
                int rm = gm + half * 8;
                float v0 = acc[mf][nf][half * 2 + 0];
                float v1 = acc[mf][nf][half * 2 + 1];
                long long addr = (long long)rm * H_ + gn;
                bf16 h0, l0, h1, l1;
                bf162 hp, lp;
                if (seg == 0) {
                    g_q[addr] = v0; g_q[addr + 1] = v1;
                    split1(v0 + cb[gn], h0, l0); split1(v1 + cb[gn + 1], h1, l1);
                    hp.x = h0; hp.y = h1; lp.x = l0; lp.y = l1;
                    *reinterpret_cast<bf162*>(&g_qch[addr]) = hp;
                    *reinterpret_cast<bf162*>(&g_qcl[addr]) = lp;
                    split1(v0 + pb[gn], h0, l0); split1(v1 + pb[gn + 1], h1, l1);
                    hp.x = h0; hp.y = h1; lp.x = l0; lp.y = l1;
                    *reinterpret_cast<bf162*>(&g_qph[addr]) = hp;
                    *reinterpret_cast<bf162*>(&g_qpl[addr]) = lp;
                } else {
                    split1(v0, h0, l0); split1(v1, h1, l1);
                    hp.x = h0; hp.y = h1; lp.x = l0; lp.y = l1;
                    bf16 *dh = (seg == 1) ? g_kh : (seg == 2) ? g_vh : g_rh;
                    bf16 *dl = (seg == 1) ? g_kl : (seg == 2) ? g_vl : g_rl;
                    *reinterpret_cast<bf162*>(&dh[addr]) = hp;
                    *reinterpret_cast<bf162*>(&dl[addr]) = lp;
                }
            }
        }
    }
}

// ---------------- scores megakernel: ac + bd ----------------
__global__ void __launch_bounds__(512)
scores_kernel()
{
    int id = blockIdx.x;
    const bf16 *Ah, *Al, *Bh, *Bl;
    float* C;
    int m0, n0, ldc;
    if (id < 1024) {
        int batch = id >> 5, local = id & 31;
        int b = batch >> 4, head = batch & 15;
        long long aoff = (long long)b * QLEN_ * H_ + head * D_;
        long long boff = (long long)b * CLEN_ * H_ + head * D_;
        Ah = g_qch + aoff; Al = g_qcl + aoff;
        Bh = g_kh + boff;  Bl = g_kl + boff;
        C = g_sc + (long long)batch * QLEN_ * CLEN_;
        m0 = (local >> 3) * TM; n0 = (local & 7) * 128; ldc = CLEN_;
    } else {
        id -= 1024;
        int batch = id / 48, local = id % 48;
        int b = batch >> 4, head = batch & 15;
        long long aoff = (long long)b * QLEN_ * H_ + head * D_;
        long long boff = (long long)b * RLEN_ * H_ + head * D_;
        Ah = g_qph + aoff; Al = g_qpl + aoff;
        Bh = g_rh + boff;  Bl = g_rl + boff;
        C = g_bd + (long long)batch * QLEN_ * RLEN_;
        m0 = (local / 12) * TM; n0 = (local % 12) * 128; ldc = RLEN_;
    }

    float acc[2][4][4];
    gemm_core<1, 128>(Ah, Al, Bh, Bl, m0, n0, D_, H_, H_, acc);

    const int lane = threadIdx.x & 31;
    const int warp = threadIdx.x >> 5;
    const int wm = (warp & 3) * 32;
    const int wn = (warp >> 2) * 32;
    const int er = lane >> 2;
    const int ec = (lane & 3) * 2;
#pragma unroll
    for (int mf = 0; mf < 2; mf++) {
#pragma unroll
        for (int nf = 0; nf < 4; nf++) {
            int gm = m0 + wm + mf * 16 + er;
            int gn = n0 + wn + nf * 8 + ec;
#pragma unroll
            for (int half = 0; half < 2; half++) {
                int rm = gm + half * 8;
                float2 v; v.x = acc[mf][nf][half * 2 + 0]; v.y = acc[mf][nf][half * 2 + 1];
                *reinterpret_cast<float2*>(&C[(long long)rm * ldc + gn]) = v;
            }
        }
    }
}

// ---------------- split conversion ----------------
__global__ void split_kernel(const float4* __restrict__ src,
                             bf162* __restrict__ h, bf162* __restrict__ l, int n4)
{
    int i = blockIdx.x * blockDim.x + threadIdx.x;
    if (i >= n4) return;
    float4 v = src[i];
    bf16 h0, l0, h1, l1, h2, l2, h3, l3;
    split1(v.x, h0, l0); split1(v.y, h1, l1);
    split1(v.z, h2, l2); split1(v.w, h3, l3);
    bf162 a; a.x = h0; a.y = h1;
    bf162 b; b.x = h2; b.y = h3;
    h[2 * i] = a; h[2 * i + 1] = b;
    a.x = l0; a.y = l1; b.x = l2; b.y = l3;
    l[2 * i] = a; l[2 * i + 1] = b;
}
static void launch_split(const float* src, bf16* h, bf16* l, long long n)
{
    int n4 = (int)(n / 4);
    split_kernel<<<(n4 + 255) / 256, 256>>>(
        (const float4*)src, (bf162*)h, (bf162*)l, n4);
}

// ---------------- small kernels ----------------
__global__ void detect_seg_kernel(const unsigned char* __restrict__ p)
{
    if (threadIdx.x == 0 && blockIdx.x == 0) {
        bool f32 = false, nonalign = false;
        for (int i = 0; i < 1024; i++) {
            unsigned char c = p[i];
            if ((i & 3) == 3 && c == 0x3F) f32 = true;
            if ((i & 3) != 0 && c == 1)    nonalign = true;
        }
        g_segmode = f32 ? 0 : (nonalign ? 2 : 1);
    }
}

__global__ void build_ctx_kernel(const float* __restrict__ mems_l,
                                 const float* __restrict__ x)
{
    int idx = blockIdx.x * blockDim.x + threadIdx.x;
    if (idx >= B_ * CLEN_ * H_) return;
    int h = idx % H_;
    int j = (idx / H_) % CLEN_;
    int b = idx / (H_ * CLEN_);
    float v = (j < MLEN_) ? mems_l[((long long)b * MLEN_ + j) * H_ + h]
                          : x[((long long)b * QLEN_ + (j - MLEN_)) * H_ + h];
    bf16 hh, ll; split1(v, hh, ll);
    g_cth[idx] = hh; g_ctl[idx] = ll;
}

__global__ void ef_kernel(const float* __restrict__ sb,
                          const float* __restrict__ se_l)
{
    int bi   = blockIdx.x;
    int n    = threadIdx.x >> 5;
    int lane = threadIdx.x & 31;
    const float* qrow = g_q + (long long)bi * H_ + n * D_;
    float s0 = 0.f, s1 = 0.f;
#pragma unroll
    for (int d = lane; d < D_; d += 32) {
        float qv = qrow[d] + sb[n * D_ + d];
        s0 += qv * se_l[n * D_ + d];
        s1 += qv * se_l[NH_ * D_ + n * D_ + d];
    }
#pragma unroll
    for (int o = 16; o > 0; o >>= 1) {
        s0 += __shfl_down_sync(0xFFFFFFFFu, s0, o);
        s1 += __shfl_down_sync(0xFFFFFFFFu, s1, o);
    }
    if (lane == 0) {
        int b = bi / QLEN_;
        int i = bi - b * QLEN_;
        long long ridx = ((long long)(b * NH_ + n) * QLEN_ + i);
        g_ef[ridx]            = s0;
        g_ef[EFSTRIDE + ridx] = s1;
    }
}

__global__ void __launch_bounds__(256)
score_softmax_kernel(const float* __restrict__ mask, const void* __restrict__ seg)
{
    int row = blockIdx.x;
    int i   = row % QLEN_;
    int bn  = row / QLEN_;
    int b   = bn / NH_;
    int tid = threadIdx.x;

    long long rbase = (long long)bn * QLEN_ * CLEN_ + (long long)i * CLEN_;
    const float* ac   = g_sc + rbase;
    const float* bd   = g_bd + (long long)bn * QLEN_ * RLEN_ + (long long)i * RLEN_ + (QLEN_ - i);
    const float* mrow = mask + ((long long)b * QLEN_ + i) * CLEN_;
    long long    sbase = ((long long)b * QLEN_ + i) * (long long)CLEN_;
    float ef0 = g_ef[(long long)bn * QLEN_ + i];
    float ef1 = g_ef[EFSTRIDE + (long long)bn * QLEN_ + i];
    int mode = g_segmode;
    const float rs = 0.125f;
    int j0 = tid * 4;

    float4 ac4 = *reinterpret_cast<const float4*>(ac + j0);
    float4 mk4 = *reinterpret_cast<const float4*>(mrow + j0);
    float vals[4] = {ac4.x, ac4.y, ac4.z, ac4.w};
    float mks[4]  = {mk4.x, mk4.y, mk4.z, mk4.w};

    float lmax = -3.0e38f;
#pragma unroll
    for (int u = 0; u < 4; u++) {
        int j = j0 + u;
        bool s;
        if (mode == 2)      s = ((const unsigned char*)seg)[sbase + j] != 0;
        else if (mode == 1) s = ((const int*)seg)[sbase + j] != 0;
        else                s = ((const float*)seg)[sbase + j] != 0.f;
        float ef = s ? ef1 : ef0;
        float sc = (vals[u] + bd[j] + ef) * rs + mks[u] * (-1e30f);
        vals[u] = sc;
        lmax = fmaxf(lmax, sc);
    }

    __shared__ float red[256];
    red[tid] = lmax;
    __syncthreads();
    for (int o = 128; o > 0; o >>= 1) {
        if (tid < o) red[tid] = fmaxf(red[tid], red[tid + o]);
        __syncthreads();
    }
    float m = red[0];
    __syncthreads();

    float lsum = 0.f;
#pragma unroll
    for (int u = 0; u < 4; u++) {
        vals[u] = __expf(vals[u] - m);
        lsum += vals[u];
    }
    red[tid] = lsum;
    __syncthreads();
    for (int o = 128; o > 0; o >>= 1) {
        if (tid < o) red[tid] += red[tid + o];
        __syncthreads();
    }
    float inv = 1.f / red[0];
    bf16 h0, l0, h1, l1;
    bf162 hp, lp;
    split1(vals[0] * inv, h0, l0); split1(vals[1] * inv, h1, l1);
    hp.x = h0; hp.y = h1; lp.x = l0; lp.y = l1;
    *reinterpret_cast<bf162*>(&g_ph[rbase + j0])     = hp;
    *reinterpret_cast<bf162*>(&g_pl[rbase + j0])     = lp;
    split1(vals[2] * inv, h0, l0); split1(vals[3] * inv, h1, l1);
    hp.x = h0; hp.y = h1; lp.x = l0; lp.y = l1;
    *reinterpret_cast<bf162*>(&g_ph[rbase + j0 + 2]) = hp;
    *reinterpret_cast<bf162*>(&g_pl[rbase + j0 + 2]) = lp;
}

__global__ void __launch_bounds__(256)
ln_kernel(const float* __restrict__ a, const float* __restrict__ b,
          const float* __restrict__ gamma, const float* __restrict__ beta,
          float* __restrict__ out, bf16* __restrict__ oh, bf16* __restrict__ ol)
{
    int row = blockIdx.x;
    int tid = threadIdx.x;
    const float* pa = a + (long long)row * H_;
    const float* pb = b + (long long)row * H_;

    float v[4];
    float lsum = 0.f;
#pragma unroll
    for (int u = 0; u < 4; u++) {
        int j = u * 256 + tid;
        v[u] = pa[j] + pb[j];
        lsum += v[u];
    }
    __shared__ float red[256];
    red[tid] = lsum;
    __syncthreads();
    for (int o = 128; o > 0; o >>= 1) {
        if (tid < o) red[tid] += red[tid + o];
        __syncthreads();
    }
    float mu = red[0] * (1.0f / H_);
    __syncthreads();

    float lvar = 0.f;
#pragma unroll
    for (int u = 0; u < 4; u++) {
        float d = v[u] - mu;
        lvar += d * d;
    }
    red[tid] = lvar;
    __syncthreads();
    for (int o = 128; o > 0; o >>= 1) {
        if (tid < o) red[tid] += red[tid + o];
        __syncthreads();
    }
    float rstd = rsqrtf(red[0] * (1.0f / H_) + LN_EPS_);
    float* po = out + (long long)row * H_;
#pragma unroll
    for (int u = 0; u < 4; u++) {
        int j = u * 256 + tid;
        float val = (v[u] - mu) * rstd * gamma[j] + beta[j];
        po[j] = val;
        if (oh) {
            bf16 hh, ll; split1(val, hh, ll);
            oh[(long long)row * H_ + j] = hh;
            ol[(long long)row * H_ + j] = ll;
        }
    }
}

// ---------------- host orchestration ----------------
struct Ptrs {
    float *x, *q, *sc, *bd, *ao, *y;
    bf16 *xh,*xl,*peh,*pel,*ph,*pl,*vh,*vl,*ath,*atl,*yh,*yl,*mih,*mil,
         *woh,*wol,*f1h,*f1l,*f2h,*f2l,
         *wqh,*wql,*wkh,*wkl,*wvh,*wvl,*wrh,*wrl;
    bool init = false;
};

extern "C" void kernel_launch(void* const* d_in, const int* in_sizes, int n_in,
                              void* d_out, int out_size)
{
    (void)in_sizes; (void)n_in; (void)out_size;

    const float* content   = (const float*)d_in[0];
    const float* mask      = (const float*)d_in[1];
    const float* posenc    = (const float*)d_in[2];
    const void*  seg       = d_in[3];
    const float* mems      = (const float*)d_in[4];
    const float* w_q       = (const float*)d_in[5];
    const float* w_k       = (const float*)d_in[6];
    const float* w_v       = (const float*)d_in[7];
    const float* w_r       = (const float*)d_in[8];
    const float* w_o       = (const float*)d_in[9];
    const float* ffn_w1    = (const float*)d_in[10];
    const float* ffn_b1    = (const float*)d_in[11];
    const float* ffn_w2    = (const float*)d_in[12];
    const float* ffn_b2    = (const float*)d_in[13];
    const float* ln1_g     = (const float*)d_in[14];
    const float* ln1_b     = (const float*)d_in[15];
    const float* ln2_g     = (const float*)d_in[16];
    const float* ln2_b     = (const float*)d_in[17];
    const float* cbias     = (const float*)d_in[18];
    const float* pbias     = (const float*)d_in[19];
    const float* sbias     = (const float*)d_in[20];
    const float* segenc    = (const float*)d_in[21];

    static Ptrs S;
    if (!S.init) {
        cudaGetSymbolAddress((void**)&S.x,  g_x);   cudaGetSymbolAddress((void**)&S.q,  g_q);
        cudaGetSymbolAddress((void**)&S.sc, g_sc);  cudaGetSymbolAddress((void**)&S.bd, g_bd);
        cudaGetSymbolAddress((void**)&S.ao, g_ao);  cudaGetSymbolAddress((void**)&S.y,  g_y);
        cudaGetSymbolAddress((void**)&S.xh, g_xh);  cudaGetSymbolAddress((void**)&S.xl, g_xl);
        cudaGetSymbolAddress((void**)&S.peh,g_peh); cudaGetSymbolAddress((void**)&S.pel,g_pel);
        cudaGetSymbolAddress((void**)&S.ph, g_ph);  cudaGetSymbolAddress((void**)&S.pl, g_pl);
        cudaGetSymbolAddress((void**)&S.vh, g_vh);  cudaGetSymbolAddress((void**)&S.vl, g_vl);
        cudaGetSymbolAddress((void**)&S.ath,g_ath); cudaGetSymbolAddress((void**)&S.atl,g_atl);
        cudaGetSymbolAddress((void**)&S.yh, g_yh);  cudaGetSymbolAddress((void**)&S.yl, g_yl);
        cudaGetSymbolAddress((void**)&S.mih,g_mih); cudaGetSymbolAddress((void**)&S.mil,g_mil);
        cudaGetSymbolAddress((void**)&S.woh,g_woh); cudaGetSymbolAddress((void**)&S.wol,g_wol);
        cudaGetSymbolAddress((void**)&S.f1h,g_f1h); cudaGetSymbolAddress((void**)&S.f1l,g_f1l);
        cudaGetSymbolAddress((void**)&S.f2h,g_f2h); cudaGetSymbolAddress((void**)&S.f2l,g_f2l);
        cudaGetSymbolAddress((void**)&S.wqh,g_wqh); cudaGetSymbolAddress((void**)&S.wql,g_wql);
        cudaGetSymbolAddress((void**)&S.wkh,g_wkh); cudaGetSymbolAddress((void**)&S.wkl,g_wkl);
        cudaGetSymbolAddress((void**)&S.wvh,g_wvh); cudaGetSymbolAddress((void**)&S.wvl,g_wvl);
        cudaGetSymbolAddress((void**)&S.wrh,g_wrh); cudaGetSymbolAddress((void**)&S.wrl,g_wrl);
        cudaFuncSetAttribute((const void*)gemm_bf<0,128>,
            cudaFuncAttributeMaxDynamicSharedMemorySize, smem_bytes(0,128));
        cudaFuncSetAttribute((const void*)gemm_bf<1,128>,
            cudaFuncAttributeMaxDynamicSharedMemorySize, smem_bytes(1,128));
        cudaFuncSetAttribute((const void*)gemm_bf<0,64>,
            cudaFuncAttributeMaxDynamicSharedMemorySize, smem_bytes(0,64));
        cudaFuncSetAttribute((const void*)gemm_bf<1,64>,
            cudaFuncAttributeMaxDynamicSharedMemorySize, smem_bytes(1,64));
        cudaFuncSetAttribute((const void*)proj_kernel,
            cudaFuncAttributeMaxDynamicSharedMemorySize, smem_bytes(0,128));
        cudaFuncSetAttribute((const void*)scores_kernel,
            cudaFuncAttributeMaxDynamicSharedMemorySize, smem_bytes(1,128));
        S.init = true;
    }

    detect_seg_kernel<<<1, 32>>>((const unsigned char*)seg);

    launch_split(content, S.xh, S.xl, (long long)B_*QLEN_*H_);
    launch_split(posenc,  S.peh, S.pel, (long long)B_*RLEN_*H_);
    launch_split(w_q, S.wqh, S.wql, (long long)L_*H_*H_);
    launch_split(w_k, S.wkh, S.wkl, (long long)L_*H_*H_);
    launch_split(w_v, S.wvh, S.wvl, (long long)L_*H_*H_);
    launch_split(w_r, S.wrh, S.wrl, (long long)L_*H_*H_);
    launch_split(w_o, S.woh, S.wol, (long long)L_*H_*H_);
    launch_split(ffn_w1, S.f1h, S.f1l, (long long)L_*H_*F_);
    launch_split(ffn_w2, S.f2h, S.f2l, (long long)L_*F_*H_);

    const float* x = content;
    const int rowsQ = B_ * QLEN_;

    for (int l = 0; l < L_; l++) {
        long long wofs = (long long)l * H_ * H_;

        {
            int total = B_ * CLEN_ * H_;
            build_ctx_kernel<<<(total + 255) / 256, 256>>>(
                mems + (long long)l * B_ * MLEN_ * H_, x);
        }

        // fused q+k+v+r projections (+ qc/qp bias splits)
        proj_kernel<<<512, 512, smem_bytes(0,128)>>>(cbias, pbias, l);

        ef_kernel<<<B_ * QLEN_, 512>>>(sbias, segenc + (long long)l * 2 * NH_ * D_);

        // fused ac + bd scores
        scores_kernel<<<2560, 512, smem_bytes(1,128)>>>();

        score_softmax_kernel<<<B_ * NH_ * QLEN_, 256>>>(mask, seg);

        launch_bf(false, S.ph, S.pl, S.vh, S.vl,
                  nullptr, S.ath, S.atl,
                  QLEN_, D_, CLEN_, CLEN_, H_, H_,
                  nullptr, 0, B_ * NH_, NH_,
                  (long long)NH_ * QLEN_ * CLEN_, (long long)QLEN_ * CLEN_,
                  (long long)CLEN_ * H_, D_,
                  (long long)QLEN_ * H_, D_,
                  /*tn64=*/true);

        launch_bf(true, S.ath, S.atl, S.woh + wofs, S.wol + wofs,
                  S.ao, nullptr, nullptr, rowsQ, H_, H_, H_, H_, H_,
                  nullptr, 0, 1, 1, 0,0,0,0,0,0, /*tn64=*/true);

        ln_kernel<<<rowsQ, 256>>>(S.ao, x, ln1_g + l * H_, ln1_b + l * H_,
                                  S.y, S.yh, S.yl);

        launch_bf(false, S.yh, S.yl, S.f1h + (long long)l * H_ * F_, S.f1l + (long long)l * H_ * F_,
                  nullptr, S.mih, S.mil, rowsQ, F_, H_, H_, F_, F_,
                  ffn_b1 + (long long)l * F_, 1, 1, 1, 0,0,0,0,0,0);
        launch_bf(false, S.mih, S.mil, S.f2h + (long long)l * F_ * H_, S.f2l + (long long)l * F_ * H_,
                  S.ao, nullptr, nullptr, rowsQ, H_, F_, F_, H_, H_,
                  ffn_b2 + (long long)l * H_, 0, 1, 1, 0,0,0,0,0,0, /*tn64=*/true);

        float* xout = (l == L_ - 1) ? (float*)d_out : S.x;
        ln_kernel<<<rowsQ, 256>>>(S.ao, S.y, ln2_g + l * H_, ln2_b + l * H_,
                                  xout, S.xh, S.xl);

        x = S.x;
    }
}

// round 15
// speedup vs baseline: 1.3464x; 1.3464x over previous
#include <cuda_runtime.h>
#include <cuda_bf16.h>
#include <math.h>

// ---------------- problem constants ----------------
#define L_    4
#define B_    2
#define QLEN_ 512
#define MLEN_ 512
#define CLEN_ 1024
#define RLEN_ 1536
#define H_    1024
#define NH_   16
#define D_    64
#define F_    4096
#define LN_EPS_ 1e-12f

#define EFSTRIDE ((long long)B_*NH_*QLEN_)
#define PADE 1024

typedef __nv_bfloat16 bf16;
typedef __nv_bfloat162 bf162;

// ---------------- fp32 scratch ----------------
__device__ float g_x  [B_*QLEN_*H_];
__device__ float g_q  [B_*QLEN_*H_];
__device__ float g_sc [(long long)B_*NH_*QLEN_*CLEN_];
__device__ float g_bd [(long long)B_*NH_*QLEN_*RLEN_];
__device__ float g_ef [2*B_*NH_*QLEN_];
__device__ float g_ao [B_*QLEN_*H_];
__device__ float g_y  [B_*QLEN_*H_];
__device__ int   g_segmode;

// ---------------- bf16 hi/lo split scratch ----------------
__device__ bf16 g_xh [B_*QLEN_*H_+PADE],  g_xl [B_*QLEN_*H_+PADE];
__device__ bf16 g_cth[B_*CLEN_*H_+PADE],  g_ctl[B_*CLEN_*H_+PADE];
__device__ bf16 g_peh[B_*RLEN_*H_+PADE],  g_pel[B_*RLEN_*H_+PADE];
__device__ bf16 g_qch[B_*QLEN_*H_+PADE],  g_qcl[B_*QLEN_*H_+PADE];
__device__ bf16 g_qph[B_*QLEN_*H_+PADE],  g_qpl[B_*QLEN_*H_+PADE];
__device__ bf16 g_kh [B_*CLEN_*H_+PADE],  g_kl [B_*CLEN_*H_+PADE];
__device__ bf16 g_vh [B_*CLEN_*H_+PADE],  g_vl [B_*CLEN_*H_+PADE];
__device__ bf16 g_rh [B_*RLEN_*H_+PADE],  g_rl [B_*RLEN_*H_+PADE];
__device__ bf16 g_ph [(long long)B_*NH_*QLEN_*CLEN_+PADE], g_pl[(long long)B_*NH_*QLEN_*CLEN_+PADE];
__device__ bf16 g_ath[B_*QLEN_*H_+PADE],  g_atl[B_*QLEN_*H_+PADE];
__device__ bf16 g_yh [B_*QLEN_*H_+PADE],  g_yl [B_*QLEN_*H_+PADE];
__device__ bf16 g_mih[B_*QLEN_*F_+PADE],  g_mil[B_*QLEN_*F_+PADE];
// weights
__device__ bf16 g_wqh[L_*H_*H_+PADE], g_wql[L_*H_*H_+PADE];
__device__ bf16 g_wkh[L_*H_*H_+PADE], g_wkl[L_*H_*H_+PADE];
__device__ bf16 g_wvh[L_*H_*H_+PADE], g_wvl[L_*H_*H_+PADE];
__device__ bf16 g_wrh[L_*H_*H_+PADE], g_wrl[L_*H_*H_+PADE];
__device__ bf16 g_woh[L_*H_*H_+PADE], g_wol[L_*H_*H_+PADE];
__device__ bf16 g_f1h[L_*H_*F_+PADE], g_f1l[L_*H_*F_+PADE];
__device__ bf16 g_f2h[L_*F_*H_+PADE], g_f2l[L_*F_*H_+PADE];

__device__ __forceinline__ void split1(float v, bf16& h, bf16& l) {
    h = __float2bfloat16(v);
    l = __float2bfloat16(v - __bfloat162float(h));
}

// ---------------- tensor-core GEMM: pre-split bf16 hi/lo, cp.async, 512 threads ----
// C[M,N] = A[M,K]*B ; TB=0: B is [K,N]; TB=1: B is [N,K] (C=A*B^T).
// 128xTN_ tile, 16 warps (4m x 4n), warp tile 32 x (TN_/4).
// 3 stages of k=32; two 16-k ldmatrix/MMA passes per stage.
// Split product: AhBh + AhBl + AlBh, fp32 accumulate.
#define TM 128
#define ASTR32 40           // halfs per 32-k row (32 data + 8 pad) = 80B
#define STAGES_ 3
#define A_ST32 (128*ASTR32) // halfs per A component per stage

__device__ __forceinline__ unsigned smaddr(const void* p) {
    return (unsigned)__cvta_generic_to_shared(p);
}

#define CPA16(dst, src) asm volatile( \
    "cp.async.ca.shared.global [%0], [%1], 16;" :: "r"(dst), "l"(src))
#define CP_COMMIT() asm volatile("cp.async.commit_group;")
#define CP_WAIT1()  asm volatile("cp.async.wait_group 1;")

#define LDSM_X4(r, a) asm volatile( \
    "ldmatrix.sync.aligned.m8n8.x4.shared.b16 {%0,%1,%2,%3}, [%4];" \
    : "=r"((r)[0]), "=r"((r)[1]), "=r"((r)[2]), "=r"((r)[3]) : "r"(a))
#define LDSM_X2(r, a) asm volatile( \
    "ldmatrix.sync.aligned.m8n8.x2.shared.b16 {%0,%1}, [%2];" \
    : "=r"((r)[0]), "=r"((r)[1]) : "r"(a))
#define LDSM_X2T(r, a) asm volatile( \
    "ldmatrix.sync.aligned.m8n8.x2.trans.shared.b16 {%0,%1}, [%2];" \
    : "=r"((r)[0]), "=r"((r)[1]) : "r"(a))
#define MMA_BF16(c, a, b) asm volatile( \
    "mma.sync.aligned.m16n8k16.row.col.f32.bf16.bf16.f32 " \
    "{%0,%1,%2,%3}, {%4,%5,%6,%7}, {%8,%9}, {%0,%1,%2,%3};" \
    : "+f"((c)[0]), "+f"((c)[1]), "+f"((c)[2]), "+f"((c)[3]) \
    : "r"((a)[0]), "r"((a)[1]), "r"((a)[2]), "r"((a)[3]), "r"((b)[0]), "r"((b)[1]))

template<int TB, int TN_>
__global__ void __launch_bounds__(512)
gemm_bf(const bf16* __restrict__ Ah, const bf16* __restrict__ Al,
        const bf16* __restrict__ Bh, const bf16* __restrict__ Bl,
        float* __restrict__ C, bf16* __restrict__ Ch, bf16* __restrict__ Cl,
        int M, int N, int K, int lda, int ldb, int ldc,
        const float* __restrict__ bias, int relu,
        int inner,
        long long oAo, long long oAi, long long oBo, long long oBi,
        long long oCo, long long oCi)
{
    constexpr int WN   = TN_ / 4;                  // warp n-width (32 or 16)
    constexpr int NF   = WN / 8;                   // n-fragments per warp (4 or 2)
    constexpr int BSTR = TN_ + 8;                  // TB=0 row stride (halfs)
    constexpr int BS   = (TB == 0) ? (32 * BSTR) : A_ST32;

    int z  = blockIdx.z;
    int zo = z / inner;
    int zi = z - zo * inner;
    Ah += zo * oAo + zi * oAi;
    Al += zo * oAo + zi * oAi;
    Bh += zo * oBo + zi * oBi;
    Bl += zo * oBo + zi * oBi;
    long long cofs = zo * oCo + zi * oCi;
    if (C)  C  += cofs;
    if (Ch) { Ch += cofs; Cl += cofs; }

    extern __shared__ __align__(16) unsigned char dsm_raw[];
    bf16* sAp = reinterpret_cast<bf16*>(dsm_raw);          // [STAGES][2][A_ST32]
    bf16* sBp = sAp + STAGES_ * 2 * A_ST32;                // [STAGES][2][BS]

    const int t    = threadIdx.x;
    const int lane = t & 31;
    const int warp = t >> 5;          // 0..15
    const int m0 = blockIdx.y * TM;
    const int n0 = blockIdx.x * TN_;
    const int wm = (warp & 3) * 32;   // warp tile: 32 rows x WN cols
    const int wn = (warp >> 2) * WN;

    float acc[2][NF][4];
#pragma unroll
    for (int mf = 0; mf < 2; mf++)
#pragma unroll
        for (int nf = 0; nf < NF; nf++)
#pragma unroll
            for (int e = 0; e < 4; e++) acc[mf][nf][e] = 0.f;

    // loader coords (512 threads)
    const int ar  = t >> 2;           // 0..127 (A rows; TB=1 B rows)
    const int ak8 = (t & 3) * 8;      // 4 chunks of 8 halfs across 32-k
    const int b0r = t >> 4;           // 0..31 (TB=0 TN128 k-rows)
    const int b0c = (t & 15) * 8;
    const int b4r = (t & 255) >> 3;   // 0..31 (TB=0 TN64, half threads)
    const int b4c = (t & 7) * 8;

    auto issue = [&](int st, int k0) {
        {
            unsigned d = smaddr(sAp + (st * 2) * A_ST32 + ar * ASTR32 + ak8);
            CPA16(d, Ah + (long long)(m0 + ar) * lda + k0 + ak8);
            CPA16(d + A_ST32 * 2, Al + (long long)(m0 + ar) * lda + k0 + ak8);
        }
        if (TB == 0) {
            if (TN_ == 128) {
                unsigned d = smaddr(sBp + (st * 2) * BS + b0r * BSTR + b0c);
                CPA16(d, Bh + (long long)(k0 + b0r) * ldb + n0 + b0c);
                CPA16(d + BS * 2, Bl + (long long)(k0 + b0r) * ldb + n0 + b0c);
            } else if (t < 256) {
                unsigned d = smaddr(sBp + (st * 2) * BS + b4r * BSTR + b4c);
                CPA16(d, Bh + (long long)(k0 + b4r) * ldb + n0 + b4c);
                CPA16(d + BS * 2, Bl + (long long)(k0 + b4r) * ldb + n0 + b4c);
            }
        } else {
            unsigned d = smaddr(sBp + (st * 2) * BS + ar * ASTR32 + ak8);
            CPA16(d, Bh + (long long)(n0 + ar) * ldb + k0 + ak8);
            CPA16(d + BS * 2, Bl + (long long)(n0 + ar) * ldb + k0 + ak8);
        }
        CP_COMMIT();
    };

    auto compute = [&](int st) {
        bf16* A0 = sAp + (st * 2) * A_ST32;
        bf16* B0 = sBp + (st * 2) * BS;
#pragma unroll
        for (int p = 0; p < 2; p++) {
            unsigned aHi = smaddr(A0 + (wm + (lane & 15)) * ASTR32 + p * 16 + (lane >> 4) * 8);
            unsigned aLo = aHi + A_ST32 * 2;
            unsigned bHi = (TB == 0)
                ? smaddr(B0 + (p * 16 + (lane & 15)) * BSTR + wn)
                : smaddr(B0 + (wn + (lane & 7)) * ASTR32 + p * 16 + ((lane >> 3) & 1) * 8);
            unsigned bLo = bHi + BS * 2;

            unsigned ah[2][4], bh[NF][2], bl[NF][2];
#pragma unroll
            for (int mf = 0; mf < 2; mf++) LDSM_X4(ah[mf], aHi + mf * (16 * ASTR32 * 2));
#pragma unroll
            for (int nf = 0; nf < NF; nf++) {
                if (TB == 0) {
                    LDSM_X2T(bh[nf], bHi + nf * 16);
                    LDSM_X2T(bl[nf], bLo + nf * 16);
                } else {
                    LDSM_X2(bh[nf], bHi + nf * (8 * ASTR32 * 2));
                    LDSM_X2(bl[nf], bLo + nf * (8 * ASTR32 * 2));
                }
            }
#pragma unroll
            for (int mf = 0; mf < 2; mf++)
#pragma unroll
                for (int nf = 0; nf < NF; nf++)
                    MMA_BF16(acc[mf][nf], ah[mf], bh[nf]);
#pragma unroll
            for (int mf = 0; mf < 2; mf++)
#pragma unroll
                for (int nf = 0; nf < NF; nf++)
                    MMA_BF16(acc[mf][nf], ah[mf], bl[nf]);
#pragma unroll
            for (int mf = 0; mf < 2; mf++) LDSM_X4(ah[mf], aLo + mf * (16 * ASTR32 * 2));
#pragma unroll
            for (int mf = 0; mf < 2; mf++)
#pragma unroll
                for (int nf = 0; nf < NF; nf++)
                    MMA_BF16(acc[mf][nf], ah[mf], bh[nf]);
        }
    };

    const int kT = K / 32;
    int issued = 0;
    for (; issued < STAGES_ - 1 && issued < kT; issued++) issue(issued, issued * 32);

    for (int i = 0; i < kT; i++) {
        CP_WAIT1();
        __syncthreads();
        compute(i % STAGES_);
        if (issued < kT) { issue(issued % STAGES_, issued * 32); issued++; }
        else             { CP_COMMIT(); }
    }

    // epilogue
    const int er = lane >> 2;
    const int ec = (lane & 3) * 2;
#pragma unroll
    for (int mf = 0; mf < 2; mf++) {
#pragma unroll
        for (int nf = 0; nf < NF; nf++) {
            int gm = m0 + wm + mf * 16 + er;
            int gn = n0 + wn + nf * 8 + ec;
#pragma unroll
            for (int half = 0; half < 2; half++) {
                int rm = gm + half * 8;
                if (rm >= M) continue;
                float v0 = acc[mf][nf][half * 2 + 0];
                float v1 = acc[mf][nf][half * 2 + 1];
                if (bias) { if (gn < N) v0 += bias[gn]; if (gn + 1 < N) v1 += bias[gn + 1]; }
                if (relu) { v0 = fmaxf(v0, 0.f); v1 = fmaxf(v1, 0.f); }
                if (gn < N) {
                    if (C) {
                        C[(long long)rm * ldc + gn] = v0;
                        if (gn + 1 < N) C[(long long)rm * ldc + gn + 1] = v1;
                    }
                    if (Ch && gn + 1 < N) {
                        bf16 h0, l0, h1, l1;
                        split1(v0, h0, l0); split1(v1, h1, l1);
                        bf162 hp; hp.x = h0; hp.y = h1;
                        bf162 lp; lp.x = l0; lp.y = l1;
                        *reinterpret_cast<bf162*>(&Ch[(long long)rm * ldc + gn]) = hp;
                        *reinterpret_cast<bf162*>(&Cl[(long long)rm * ldc + gn]) = lp;
                    }
                }
            }
        }
    }
}

static inline int smem_bytes(int tb, int tn) {
    int bs = (tb == 0) ? 32 * (tn + 8) : A_ST32;
    return STAGES_ * 2 * (A_ST32 + bs) * 2;
}

static void launch_bf(bool transB,
                      const bf16* Ah, const bf16* Al,
                      const bf16* Bh, const bf16* Bl,
                      float* C, bf16* Ch, bf16* Cl,
                      int M, int N, int K, int lda, int ldb, int ldc,
                      const float* bias, int relu,
                      int batches, int inner,
                      long long oAo, long long oAi,
                      long long oBo, long long oBi,
                      long long oCo, long long oCi,
                      bool tn64 = false)
{
    int tn = tn64 ? 64 : 128;
    dim3 grid((N + tn - 1) / tn, (M + TM - 1) / TM, batches);
    int sm = smem_bytes(transB ? 1 : 0, tn);
    if (transB) {
        if (tn64)
            gemm_bf<1,64><<<grid, 512, sm>>>(Ah, Al, Bh, Bl, C, Ch, Cl, M, N, K, lda, ldb, ldc,
                                             bias, relu, inner, oAo, oAi, oBo, oBi, oCo, oCi);
        else
            gemm_bf<1,128><<<grid, 512, sm>>>(Ah, Al, Bh, Bl, C, Ch, Cl, M, N, K, lda, ldb, ldc,
                                              bias, relu, inner, oAo, oAi, oBo, oBi, oCo, oCi);
    } else {
        if (tn64)
            gemm_bf<0,64><<<grid, 512, sm>>>(Ah, Al, Bh, Bl, C, Ch, Cl, M, N, K, lda, ldb, ldc,
                                             bias, relu, inner, oAo, oAi, oBo, oBi, oCo, oCi);
        else
            gemm_bf<0,128><<<grid, 512, sm>>>(Ah, Al, Bh, Bl, C, Ch, Cl, M, N, K, lda, ldb, ldc,
                                              bias, relu, inner, oAo, oAi, oBo, oBi, oCo, oCi);
    }
}

// ---------------- fused split conversion: all 9 arrays in ONE launch ----------------
#define NSEG_ 9
struct SplitJobs {
    const float4* src[NSEG_];
    bf162* h[NSEG_];
    bf162* l[NSEG_];
    long long cum[NSEG_ + 1];   // cumulative n4 boundaries
};

__global__ void __launch_bounds__(256)
split_all_kernel(SplitJobs J)
{
    long long total = J.cum[NSEG_];
    for (long long g = (long long)blockIdx.x * blockDim.x + threadIdx.x;
         g < total;
         g += (long long)gridDim.x * blockDim.x)
    {
        int s = 0;
#pragma unroll
        for (int k = 1; k < NSEG_; k++) if (g >= J.cum[k]) s = k;
        long long i = g - J.cum[s];
        float4 v = J.src[s][i];
        bf16 h0, l0, h1, l1, h2, l2, h3, l3;
        split1(v.x, h0, l0); split1(v.y, h1, l1);
        split1(v.z, h2, l2); split1(v.w, h3, l3);
        bf162 a; a.x = h0; a.y = h1;
        bf162 b; b.x = h2; b.y = h3;
        J.h[s][2 * i] = a; J.h[s][2 * i + 1] = b;
        a.x = l0; a.y = l1; b.x = l2; b.y = l3;
        J.l[s][2 * i] = a; J.l[s][2 * i + 1] = b;
    }
}

// ---------------- small kernels ----------------
__global__ void detect_seg_kernel(const unsigned char* __restrict__ p)
{
    if (threadIdx.x == 0 && blockIdx.x == 0) {
        bool f32 = false, nonalign = false;
        for (int i = 0; i < 1024; i++) {
            unsigned char c = p[i];
            if ((i & 3) == 3 && c == 0x3F) f32 = true;
            if ((i & 3) != 0 && c == 1)    nonalign = true;
        }
        g_segmode = f32 ? 0 : (nonalign ? 2 : 1);
    }
}

__global__ void build_ctx_kernel(const float* __restrict__ mems_l,
                                 const float* __restrict__ x)
{
    int idx = blockIdx.x * blockDim.x + threadIdx.x;
    if (idx >= B_ * CLEN_ * H_) return;
    int h = idx % H_;
    int j = (idx / H_) % CLEN_;
    int b = idx / (H_ * CLEN_);
    float v = (j < MLEN_) ? mems_l[((long long)b * MLEN_ + j) * H_ + h]
                          : x[((long long)b * QLEN_ + (j - MLEN_)) * H_ + h];
    bf16 hh, ll; split1(v, hh, ll);
    g_cth[idx] = hh; g_ctl[idx] = ll;
}

__global__ void make_qcp_kernel(const float* __restrict__ cb,
                                const float* __restrict__ pb)
{
    int idx = blockIdx.x * blockDim.x + threadIdx.x;
    if (idx >= B_ * QLEN_ * H_) return;
    int nd  = idx % H_;
    float q = g_q[idx];
    bf16 hh, ll;
    split1(q + cb[nd], hh, ll); g_qch[idx] = hh; g_qcl[idx] = ll;
    split1(q + pb[nd], hh, ll); g_qph[idx] = hh; g_qpl[idx] = ll;
}

__global__ void ef_kernel(const float* __restrict__ sb,
                          const float* __restrict__ se_l)
{
    int bi   = blockIdx.x;
    int n    = threadIdx.x >> 5;
    int lane = threadIdx.x & 31;
    const float* qrow = g_q + (long long)bi * H_ + n * D_;
    float s0 = 0.f, s1 = 0.f;
#pragma unroll
    for (int d = lane; d < D_; d += 32) {
        float qv = qrow[d] + sb[n * D_ + d];
        s0 += qv * se_l[n * D_ + d];
        s1 += qv * se_l[NH_ * D_ + n * D_ + d];
    }
#pragma unroll
    for (int o = 16; o > 0; o >>= 1) {
        s0 += __shfl_down_sync(0xFFFFFFFFu, s0, o);
        s1 += __shfl_down_sync(0xFFFFFFFFu, s1, o);
    }
    if (lane == 0) {
        int b = bi / QLEN_;
        int i = bi - b * QLEN_;
        long long ridx = ((long long)(b * NH_ + n) * QLEN_ + i);
        g_ef[ridx]            = s0;
        g_ef[EFSTRIDE + ridx] = s1;
    }
}

__global__ void __launch_bounds__(256)
score_softmax_kernel(const float* __restrict__ mask, const void* __restrict__ seg)
{
    int row = blockIdx.x;
    int i   = row % QLEN_;
    int bn  = row / QLEN_;
    int b   = bn / NH_;
    int tid = threadIdx.x;

    long long rbase = (long long)bn * QLEN_ * CLEN_ + (long long)i * CLEN_;
    const float* ac   = g_sc + rbase;
    const float* bd   = g_bd + (long long)bn * QLEN_ * RLEN_ + (long long)i * RLEN_ + (QLEN_ - i);
    const float* mrow = mask + ((long long)b * QLEN_ + i) * CLEN_;
    long long    sbase = ((long long)b * QLEN_ + i) * (long long)CLEN_;
    float ef0 = g_ef[(long long)bn * QLEN_ + i];
    float ef1 = g_ef[EFSTRIDE + (long long)bn * QLEN_ + i];
    int mode = g_segmode;
    const float rs = 0.125f;

    float vals[4];
    float lmax = -3.0e38f;
#pragma unroll
    for (int u = 0; u < 4; u++) {
        int j = u * 256 + tid;
        bool s;
        if (mode == 2)      s = ((const unsigned char*)seg)[sbase + j] != 0;
        else if (mode == 1) s = ((const int*)seg)[sbase + j] != 0;
        else                s = ((const float*)seg)[sbase + j] != 0.f;
        float ef = s ? ef1 : ef0;
        float sc = (ac[j] + bd[j] + ef) * rs + mrow[j] * (-1e30f);
        vals[u] = sc;
        lmax = fmaxf(lmax, sc);
    }

    __shared__ float red[256];
    red[tid] = lmax;
    __syncthreads();
    for (int o = 128; o > 0; o >>= 1) {
        if (tid < o) red[tid] = fmaxf(red[tid], red[tid + o]);
        __syncthreads();
    }
    float m = red[0];
    __syncthreads();

    float lsum = 0.f;
#pragma unroll
    for (int u = 0; u < 4; u++) {
        vals[u] = __expf(vals[u] - m);
        lsum += vals[u];
    }
    red[tid] = lsum;
    __syncthreads();
    for (int o = 128; o > 0; o >>= 1) {
        if (tid < o) red[tid] += red[tid + o];
        __syncthreads();
    }
    float inv = 1.f / red[0];
#pragma unroll
    for (int u = 0; u < 4; u++) {
        int j = u * 256 + tid;
        bf16 hh, ll; split1(vals[u] * inv, hh, ll);
        g_ph[rbase + j] = hh;
        g_pl[rbase + j] = ll;
    }
}

__global__ void __launch_bounds__(256)
ln_kernel(const float* __restrict__ a, const float* __restrict__ b,
          const float* __restrict__ gamma, const float* __restrict__ beta,
          float* __restrict__ out, bf16* __restrict__ oh, bf16* __restrict__ ol)
{
    int row = blockIdx.x;
    int tid = threadIdx.x;
    const float* pa = a + (long long)row * H_;
    const float* pb = b + (long long)row * H_;

    float v[4];
    float lsum = 0.f;
#pragma unroll
    for (int u = 0; u < 4; u++) {
        int j = u * 256 + tid;
        v[u] = pa[j] + pb[j];
        lsum += v[u];
    }
    __shared__ float red[256];
    red[tid] = lsum;
    __syncthreads();
    for (int o = 128; o > 0; o >>= 1) {
        if (tid < o) red[tid] += red[tid + o];
        __syncthreads();
    }
    float mu = red[0] * (1.0f / H_);
    __syncthreads();

    float lvar = 0.f;
#pragma unroll
    for (int u = 0; u < 4; u++) {
        float d = v[u] - mu;
        lvar += d * d;
    }
    red[tid] = lvar;
    __syncthreads();
    for (int o = 128; o > 0; o >>= 1) {
        if (tid < o) red[tid] += red[tid + o];
        __syncthreads();
    }
    float rstd = rsqrtf(red[0] * (1.0f / H_) + LN_EPS_);
    float* po = out + (long long)row * H_;
#pragma unroll
    for (int u = 0; u < 4; u++) {
        int j = u * 256 + tid;
        float val = (v[u] - mu) * rstd * gamma[j] + beta[j];
        po[j] = val;
        if (oh) {
            bf16 hh, ll; split1(val, hh, ll);
            oh[(long long)row * H_ + j] = hh;
            ol[(long long)row * H_ + j] = ll;
        }
    }
}

// ---------------- host orchestration ----------------
struct Ptrs {
    float *x, *q, *sc, *bd, *ao, *y;
    bf16 *xh,*xl,*cth,*ctl,*peh,*pel,*qch,*qcl,*qph,*qpl,*kh,*kl,*vh,*vl,*rh,*rl,
         *ph,*pl,*ath,*atl,*yh,*yl,*mih,*mil,
         *wqh,*wql,*wkh,*wkl,*wvh,*wvl,*wrh,*wrl,*woh,*wol,*f1h,*f1l,*f2h,*f2l;
    bool init = false;
};

extern "C" void kernel_launch(void* const* d_in, const int* in_sizes, int n_in,
                              void* d_out, int out_size)
{
    (void)in_sizes; (void)n_in; (void)out_size;

    const float* content   = (const float*)d_in[0];
    const float* mask      = (const float*)d_in[1];
    const float* posenc    = (const float*)d_in[2];
    const void*  seg       = d_in[3];
    const float* mems      = (const float*)d_in[4];
    const float* w_q       = (const float*)d_in[5];
    const float* w_k       = (const float*)d_in[6];
    const float* w_v       = (const float*)d_in[7];
    const float* w_r       = (const float*)d_in[8];
    const float* w_o       = (const float*)d_in[9];
    const float* ffn_w1    = (const float*)d_in[10];
    const float* ffn_b1    = (const float*)d_in[11];
    const float* ffn_w2    = (const float*)d_in[12];
    const float* ffn_b2    = (const float*)d_in[13];
    const float* ln1_g     = (const float*)d_in[14];
    const float* ln1_b     = (const float*)d_in[15];
    const float* ln2_g     = (const float*)d_in[16];
    const float* ln2_b     = (const float*)d_in[17];
    const float* cbias     = (const float*)d_in[18];
    const float* pbias     = (const float*)d_in[19];
    const float* sbias     = (const float*)d_in[20];
    const float* segenc    = (const float*)d_in[21];

    static Ptrs S;
    if (!S.init) {
        cudaGetSymbolAddress((void**)&S.x,  g_x);   cudaGetSymbolAddress((void**)&S.q,  g_q);
        cudaGetSymbolAddress((void**)&S.sc, g_sc);  cudaGetSymbolAddress((void**)&S.bd, g_bd);
        cudaGetSymbolAddress((void**)&S.ao, g_ao);  cudaGetSymbolAddress((void**)&S.y,  g_y);
        cudaGetSymbolAddress((void**)&S.xh, g_xh);  cudaGetSymbolAddress((void**)&S.xl, g_xl);
        cudaGetSymbolAddress((void**)&S.cth,g_cth); cudaGetSymbolAddress((void**)&S.ctl,g_ctl);
        cudaGetSymbolAddress((void**)&S.peh,g_peh); cudaGetSymbolAddress((void**)&S.pel,g_pel);
        cudaGetSymbolAddress((void**)&S.qch,g_qch); cudaGetSymbolAddress((void**)&S.qcl,g_qcl);
        cudaGetSymbolAddress((void**)&S.qph,g_qph); cudaGetSymbolAddress((void**)&S.qpl,g_qpl);
        cudaGetSymbolAddress((void**)&S.kh, g_kh);  cudaGetSymbolAddress((void**)&S.kl, g_kl);
        cudaGetSymbolAddress((void**)&S.vh, g_vh);  cudaGetSymbolAddress((void**)&S.vl, g_vl);
        cudaGetSymbolAddress((void**)&S.rh, g_rh);  cudaGetSymbolAddress((void**)&S.rl, g_rl);
        cudaGetSymbolAddress((void**)&S.ph, g_ph);  cudaGetSymbolAddress((void**)&S.pl, g_pl);
        cudaGetSymbolAddress((void**)&S.ath,g_ath); cudaGetSymbolAddress((void**)&S.atl,g_atl);
        cudaGetSymbolAddress((void**)&S.yh, g_yh);  cudaGetSymbolAddress((void**)&S.yl, g_yl);
        cudaGetSymbolAddress((void**)&S.mih,g_mih); cudaGetSymbolAddress((void**)&S.mil,g_mil);
        cudaGetSymbolAddress((void**)&S.wqh,g_wqh); cudaGetSymbolAddress((void**)&S.wql,g_wql);
        cudaGetSymbolAddress((void**)&S.wkh,g_wkh); cudaGetSymbolAddress((void**)&S.wkl,g_wkl);
        cudaGetSymbolAddress((void**)&S.wvh,g_wvh); cudaGetSymbolAddress((void**)&S.wvl,g_wvl);
        cudaGetSymbolAddress((void**)&S.wrh,g_wrh); cudaGetSymbolAddress((void**)&S.wrl,g_wrl);
        cudaGetSymbolAddress((void**)&S.woh,g_woh); cudaGetSymbolAddress((void**)&S.wol,g_wol);
        cudaGetSymbolAddress((void**)&S.f1h,g_f1h); cudaGetSymbolAddress((void**)&S.f1l,g_f1l);
        cudaGetSymbolAddress((void**)&S.f2h,g_f2h); cudaGetSymbolAddress((void**)&S.f2l,g_f2l);
        cudaFuncSetAttribute((const void*)gemm_bf<0,128>,
            cudaFuncAttributeMaxDynamicSharedMemorySize, smem_bytes(0,128));
        cudaFuncSetAttribute((const void*)gemm_bf<1,128>,
            cudaFuncAttributeMaxDynamicSharedMemorySize, smem_bytes(1,128));
        cudaFuncSetAttribute((const void*)gemm_bf<0,64>,
            cudaFuncAttributeMaxDynamicSharedMemorySize, smem_bytes(0,64));
        cudaFuncSetAttribute((const void*)gemm_bf<1,64>,
            cudaFuncAttributeMaxDynamicSharedMemorySize, smem_bytes(1,64));
        S.init = true;
    }

    detect_seg_kernel<<<1, 32>>>((const unsigned char*)seg);

    // fused split of all static arrays (content, posenc, 7 weight tensors)
    {
        SplitJobs J;
        const float* srcs[NSEG_] = {content, posenc, w_q, w_k, w_v, w_r, w_o, ffn_w1, ffn_w2};
        bf16* hs[NSEG_] = {S.xh, S.peh, S.wqh, S.wkh, S.wvh, S.wrh, S.woh, S.f1h, S.f2h};
        bf16* ls[NSEG_] = {S.xl, S.pel, S.wql, S.wkl, S.wvl, S.wrl, S.wol, S.f1l, S.f2l};
        long long ns[NSEG_] = {
            (long long)B_*QLEN_*H_, (long long)B_*RLEN_*H_,
            (long long)L_*H_*H_, (long long)L_*H_*H_, (long long)L_*H_*H_,
            (long long)L_*H_*H_, (long long)L_*H_*H_,
            (long long)L_*H_*F_, (long long)L_*F_*H_};
        long long c = 0;
        for (int s = 0; s < NSEG_; s++) {
            J.src[s] = (const float4*)srcs[s];
            J.h[s]   = (bf162*)hs[s];
            J.l[s]   = (bf162*)ls[s];
            J.cum[s] = c;
            c += ns[s] / 4;
        }
        J.cum[NSEG_] = c;
        int blocks = 148 * 16;   // grid-stride, ~2 waves of full chip
        split_all_kernel<<<blocks, 256>>>(J);
    }

    const float* x = content;
    const int rowsQ = B_ * QLEN_;
    const int rowsC = B_ * CLEN_;
    const int rowsR = B_ * RLEN_;

    for (int l = 0; l < L_; l++) {
        long long wofs = (long long)l * H_ * H_;

        {
            int total = B_ * CLEN_ * H_;
            build_ctx_kernel<<<(total + 255) / 256, 256>>>(
                mems + (long long)l * B_ * MLEN_ * H_, x);
        }

        // q proj (TN=64 -> 128 CTAs)
        launch_bf(false, S.xh, S.xl, S.wqh + wofs, S.wql + wofs,
                  S.q, nullptr, nullptr, rowsQ, H_, H_, H_, H_, H_,
                  nullptr, 0, 1, 1, 0,0,0,0,0,0, /*tn64=*/true);
        launch_bf(false, S.cth, S.ctl, S.wkh + wofs, S.wkl + wofs,
                  nullptr, S.kh, S.kl, rowsC, H_, H_, H_, H_, H_,
                  nullptr, 0, 1, 1, 0,0,0,0,0,0);
        launch_bf(false, S.cth, S.ctl, S.wvh + wofs, S.wvl + wofs,
                  nullptr, S.vh, S.vl, rowsC, H_, H_, H_, H_, H_,
                  nullptr, 0, 1, 1, 0,0,0,0,0,0);
        launch_bf(false, S.peh, S.pel, S.wrh + wofs, S.wrl + wofs,
                  nullptr, S.rh, S.rl, rowsR, H_, H_, H_, H_, H_,
                  nullptr, 0, 1, 1, 0,0,0,0,0,0);

        {
            int total = B_ * QLEN_ * H_;
            make_qcp_kernel<<<(total + 255) / 256, 256>>>(cbias, pbias);
        }
        ef_kernel<<<B_ * QLEN_, 512>>>(sbias, segenc + (long long)l * 2 * NH_ * D_);

        launch_bf(true, S.qch, S.qcl, S.kh, S.kl,
                  S.sc, nullptr, nullptr,
                  QLEN_, CLEN_, D_, H_, H_, CLEN_,
                  nullptr, 0, B_ * NH_, NH_,
                  (long long)QLEN_ * H_, D_,
                  (long long)CLEN_ * H_, D_,
                  (long long)NH_ * QLEN_ * CLEN_, (long long)QLEN_ * CLEN_);

        launch_bf(true, S.qph, S.qpl, S.rh, S.rl,
                  S.bd, nullptr, nullptr,
                  QLEN_, RLEN_, D_, H_, H_, RLEN_,
                  nullptr, 0, B_ * NH_, NH_,
                  (long long)QLEN_ * H_, D_,
                  (long long)RLEN_ * H_, D_,
                  (long long)NH_ * QLEN_ * RLEN_, (long long)QLEN_ * RLEN_);

        score_softmax_kernel<<<B_ * NH_ * QLEN_, 256>>>(mask, seg);

        launch_bf(false, S.ph, S.pl, S.vh, S.vl,
                  nullptr, S.ath, S.atl,
                  QLEN_, D_, CLEN_, CLEN_, H_, H_,
                  nullptr, 0, B_ * NH_, NH_,
                  (long long)NH_ * QLEN_ * CLEN_, (long long)QLEN_ * CLEN_,
                  (long long)CLEN_ * H_, D_,
                  (long long)QLEN_ * H_, D_,
                  /*tn64=*/true);

        // out proj (TN=64 -> 128 CTAs)
        launch_bf(true, S.ath, S.atl, S.woh + wofs, S.wol + wofs,
                  S.ao, nullptr, nullptr, rowsQ, H_, H_, H_, H_, H_,
                  nullptr, 0, 1, 1, 0,0,0,0,0,0, /*tn64=*/true);

        ln_kernel<<<rowsQ, 256>>>(S.ao, x, ln1_g + l * H_, ln1_b + l * H_,
                                  S.y, S.yh, S.yl);

        launch_bf(false, S.yh, S.yl, S.f1h + (long long)l * H_ * F_, S.f1l + (long long)l * H_ * F_,
                  nullptr, S.mih, S.mil, rowsQ, F_, H_, H_, F_, F_,
                  ffn_b1 + (long long)l * F_, 1, 1, 1, 0,0,0,0,0,0);
        // ffn2 (TN=64 -> 128 CTAs)
        launch_bf(false, S.mih, S.mil, S.f2h + (long long)l * F_ * H_, S.f2l + (long long)l * F_ * H_,
                  S.ao, nullptr, nullptr, rowsQ, H_, F_, F_, H_, H_,
                  ffn_b2 + (long long)l * H_, 0, 1, 1, 0,0,0,0,0,0, /*tn64=*/true);

        float* xout = (l == L_ - 1) ? (float*)d_out : S.x;
        ln_kernel<<<rowsQ, 256>>>(S.ao, S.y, ln2_g + l * H_, ln2_b + l * H_,
                                  xout, S.xh, S.xl);

        x = S.x;
    }
}

// round 16
// speedup vs baseline: 1.3788x; 1.0241x over previous
#include <cuda_runtime.h>
#include <cuda_bf16.h>
#include <math.h>

// ---------------- problem constants ----------------
#define L_    4
#define B_    2
#define QLEN_ 512
#define MLEN_ 512
#define CLEN_ 1024
#define RLEN_ 1536
#define H_    1024
#define NH_   16
#define D_    64
#define F_    4096
#define LN_EPS_ 1e-12f

#define EFSTRIDE ((long long)B_*NH_*QLEN_)
#define PADE 1024

typedef __nv_bfloat16 bf16;
typedef __nv_bfloat162 bf162;

// ---------------- fp32 scratch ----------------
__device__ float g_x  [B_*QLEN_*H_];
__device__ float g_q  [B_*QLEN_*H_];
__device__ float g_sc [(long long)B_*NH_*QLEN_*CLEN_];
__device__ float g_bd [(long long)B_*NH_*QLEN_*RLEN_];
__device__ float g_ef [2*B_*NH_*QLEN_];
__device__ float g_ao [B_*QLEN_*H_];
__device__ float g_y  [B_*QLEN_*H_];
__device__ int   g_segmode;

// ---------------- bf16 hi/lo split scratch ----------------
__device__ bf16 g_xh [B_*QLEN_*H_+PADE],  g_xl [B_*QLEN_*H_+PADE];
__device__ bf16 g_cth[B_*CLEN_*H_+PADE],  g_ctl[B_*CLEN_*H_+PADE];
__device__ bf16 g_peh[B_*RLEN_*H_+PADE],  g_pel[B_*RLEN_*H_+PADE];
__device__ bf16 g_qch[B_*QLEN_*H_+PADE],  g_qcl[B_*QLEN_*H_+PADE];
__device__ bf16 g_qph[B_*QLEN_*H_+PADE],  g_qpl[B_*QLEN_*H_+PADE];
__device__ bf16 g_kh [B_*CLEN_*H_+PADE],  g_kl [B_*CLEN_*H_+PADE];
__device__ bf16 g_vh [B_*CLEN_*H_+PADE],  g_vl [B_*CLEN_*H_+PADE];
__device__ bf16 g_rh [B_*RLEN_*H_+PADE],  g_rl [B_*RLEN_*H_+PADE];
__device__ bf16 g_ph [(long long)B_*NH_*QLEN_*CLEN_+PADE], g_pl[(long long)B_*NH_*QLEN_*CLEN_+PADE];
__device__ bf16 g_ath[B_*QLEN_*H_+PADE],  g_atl[B_*QLEN_*H_+PADE];
__device__ bf16 g_yh [B_*QLEN_*H_+PADE],  g_yl [B_*QLEN_*H_+PADE];
__device__ bf16 g_mih[B_*QLEN_*F_+PADE],  g_mil[B_*QLEN_*F_+PADE];
// weights
__device__ bf16 g_wqh[L_*H_*H_+PADE], g_wql[L_*H_*H_+PADE];
__device__ bf16 g_wkh[L_*H_*H_+PADE], g_wkl[L_*H_*H_+PADE];
__device__ bf16 g_wvh[L_*H_*H_+PADE], g_wvl[L_*H_*H_+PADE];
__device__ bf16 g_wrh[L_*H_*H_+PADE], g_wrl[L_*H_*H_+PADE];
__device__ bf16 g_woh[L_*H_*H_+PADE], g_wol[L_*H_*H_+PADE];
__device__ bf16 g_f1h[L_*H_*F_+PADE], g_f1l[L_*H_*F_+PADE];
__device__ bf16 g_f2h[L_*F_*H_+PADE], g_f2l[L_*F_*H_+PADE];

__device__ __forceinline__ void split1(float v, bf16& h, bf16& l) {
    h = __float2bfloat16(v);
    l = __float2bfloat16(v - __bfloat162float(h));
}

// ---------------- tensor-core GEMM: pre-split bf16 hi/lo, cp.async, 512 threads ----
// C[M,N] = A[M,K]*B ; TB=0: B is [K,N]; TB=1: B is [N,K] (C=A*B^T).
// 128xTN_ tile, 16 warps (4m x 4n), warp tile 32 x (TN_/4).
// NS pipeline stages of k=32 (NS=2 used only for K=64: both tiles issued upfront).
// Split product: AhBh + AhBl + AlBh, fp32 accumulate.
#define TM 128
#define ASTR32 40           // halfs per 32-k row (32 data + 8 pad) = 80B
#define A_ST32 (128*ASTR32) // halfs per A component per stage

__device__ __forceinline__ unsigned smaddr(const void* p) {
    return (unsigned)__cvta_generic_to_shared(p);
}

#define CPA16(dst, src) asm volatile( \
    "cp.async.ca.shared.global [%0], [%1], 16;" :: "r"(dst), "l"(src))
#define CP_COMMIT() asm volatile("cp.async.commit_group;")
#define CP_WAIT1()  asm volatile("cp.async.wait_group 1;")
#define CP_WAIT0()  asm volatile("cp.async.wait_group 0;")

#define LDSM_X4(r, a) asm volatile( \
    "ldmatrix.sync.aligned.m8n8.x4.shared.b16 {%0,%1,%2,%3}, [%4];" \
    : "=r"((r)[0]), "=r"((r)[1]), "=r"((r)[2]), "=r"((r)[3]) : "r"(a))
#define LDSM_X2(r, a) asm volatile( \
    "ldmatrix.sync.aligned.m8n8.x2.shared.b16 {%0,%1}, [%2];" \
    : "=r"((r)[0]), "=r"((r)[1]) : "r"(a))
#define LDSM_X2T(r, a) asm volatile( \
    "ldmatrix.sync.aligned.m8n8.x2.trans.shared.b16 {%0,%1}, [%2];" \
    : "=r"((r)[0]), "=r"((r)[1]) : "r"(a))
#define MMA_BF16(c, a, b) asm volatile( \
    "mma.sync.aligned.m16n8k16.row.col.f32.bf16.bf16.f32 " \
    "{%0,%1,%2,%3}, {%4,%5,%6,%7}, {%8,%9}, {%0,%1,%2,%3};" \
    : "+f"((c)[0]), "+f"((c)[1]), "+f"((c)[2]), "+f"((c)[3]) \
    : "r"((a)[0]), "r"((a)[1]), "r"((a)[2]), "r"((a)[3]), "r"((b)[0]), "r"((b)[1]))

template<int TB, int TN_, int NS>
__global__ void __launch_bounds__(512)
gemm_bf(const bf16* __restrict__ Ah, const bf16* __restrict__ Al,
        const bf16* __restrict__ Bh, const bf16* __restrict__ Bl,
        float* __restrict__ C, bf16* __restrict__ Ch, bf16* __restrict__ Cl,
        int M, int N, int K, int lda, int ldb, int ldc,
        const float* __restrict__ bias, int relu,
        int inner,
        long long oAo, long long oAi, long long oBo, long long oBi,
        long long oCo, long long oCi)
{
    constexpr int WN   = TN_ / 4;                  // warp n-width (32 or 16)
    constexpr int NF   = WN / 8;                   // n-fragments per warp (4 or 2)
    constexpr int BSTR = TN_ + 8;                  // TB=0 row stride (halfs)
    constexpr int BS   = (TB == 0) ? (32 * BSTR) : A_ST32;

    int z  = blockIdx.z;
    int zo = z / inner;
    int zi = z - zo * inner;
    Ah += zo * oAo + zi * oAi;
    Al += zo * oAo + zi * oAi;
    Bh += zo * oBo + zi * oBi;
    Bl += zo * oBo + zi * oBi;
    long long cofs = zo * oCo + zi * oCi;
    if (C)  C  += cofs;
    if (Ch) { Ch += cofs; Cl += cofs; }

    extern __shared__ __align__(16) unsigned char dsm_raw[];
    bf16* sAp = reinterpret_cast<bf16*>(dsm_raw);          // [NS][2][A_ST32]
    bf16* sBp = sAp + NS * 2 * A_ST32;                     // [NS][2][BS]

    const int t    = threadIdx.x;
    const int lane = t & 31;
    const int warp = t >> 5;          // 0..15
    const int m0 = blockIdx.y * TM;
    const int n0 = blockIdx.x * TN_;
    const int wm = (warp & 3) * 32;   // warp tile: 32 rows x WN cols
    const int wn = (warp >> 2) * WN;

    float acc[2][NF][4];
#pragma unroll
    for (int mf = 0; mf < 2; mf++)
#pragma unroll
        for (int nf = 0; nf < NF; nf++)
#pragma unroll
            for (int e = 0; e < 4; e++) acc[mf][nf][e] = 0.f;

    // loader coords (512 threads)
    const int ar  = t >> 2;           // 0..127 (A rows; TB=1 B rows)
    const int ak8 = (t & 3) * 8;      // 4 chunks of 8 halfs across 32-k
    const int b0r = t >> 4;           // 0..31 (TB=0 TN128 k-rows)
    const int b0c = (t & 15) * 8;
    const int b4r = (t & 255) >> 3;   // 0..31 (TB=0 TN64, half threads)
    const int b4c = (t & 7) * 8;

    auto issue = [&](int st, int k0) {
        {
            unsigned d = smaddr(sAp + (st * 2) * A_ST32 + ar * ASTR32 + ak8);
            CPA16(d, Ah + (long long)(m0 + ar) * lda + k0 + ak8);
            CPA16(d + A_ST32 * 2, Al + (long long)(m0 + ar) * lda + k0 + ak8);
        }
        if (TB == 0) {
            if (TN_ == 128) {
                unsigned d = smaddr(sBp + (st * 2) * BS + b0r * BSTR + b0c);
                CPA16(d, Bh + (long long)(k0 + b0r) * ldb + n0 + b0c);
                CPA16(d + BS * 2, Bl + (long long)(k0 + b0r) * ldb + n0 + b0c);
            } else if (t < 256) {
                unsigned d = smaddr(sBp + (st * 2) * BS + b4r * BSTR + b4c);
                CPA16(d, Bh + (long long)(k0 + b4r) * ldb + n0 + b4c);
                CPA16(d + BS * 2, Bl + (long long)(k0 + b4r) * ldb + n0 + b4c);
            }
        } else {
            unsigned d = smaddr(sBp + (st * 2) * BS + ar * ASTR32 + ak8);
            CPA16(d, Bh + (long long)(n0 + ar) * ldb + k0 + ak8);
            CPA16(d + BS * 2, Bl + (long long)(n0 + ar) * ldb + k0 + ak8);
        }
        CP_COMMIT();
    };

    auto compute = [&](int st) {
        bf16* A0 = sAp + (st * 2) * A_ST32;
        bf16* B0 = sBp + (st * 2) * BS;
#pragma unroll
        for (int p = 0; p < 2; p++) {
            unsigned aHi = smaddr(A0 + (wm + (lane & 15)) * ASTR32 + p * 16 + (lane >> 4) * 8);
            unsigned aLo = aHi + A_ST32 * 2;
            unsigned bHi = (TB == 0)
                ? smaddr(B0 + (p * 16 + (lane & 15)) * BSTR + wn)
                : smaddr(B0 + (wn + (lane & 7)) * ASTR32 + p * 16 + ((lane >> 3) & 1) * 8);
            unsigned bLo = bHi + BS * 2;

            unsigned ah[2][4], bh[NF][2], bl[NF][2];
#pragma unroll
            for (int mf = 0; mf < 2; mf++) LDSM_X4(ah[mf], aHi + mf * (16 * ASTR32 * 2));
#pragma unroll
            for (int nf = 0; nf < NF; nf++) {
                if (TB == 0) {
                    LDSM_X2T(bh[nf], bHi + nf * 16);
                    LDSM_X2T(bl[nf], bLo + nf * 16);
                } else {
                    LDSM_X2(bh[nf], bHi + nf * (8 * ASTR32 * 2));
                    LDSM_X2(bl[nf], bLo + nf * (8 * ASTR32 * 2));
                }
            }
#pragma unroll
            for (int mf = 0; mf < 2; mf++)
#pragma unroll
                for (int nf = 0; nf < NF; nf++)
                    MMA_BF16(acc[mf][nf], ah[mf], bh[nf]);
#pragma unroll
            for (int mf = 0; mf < 2; mf++)
#pragma unroll
                for (int nf = 0; nf < NF; nf++)
                    MMA_BF16(acc[mf][nf], ah[mf], bl[nf]);
#pragma unroll
            for (int mf = 0; mf < 2; mf++) LDSM_X4(ah[mf], aLo + mf * (16 * ASTR32 * 2));
#pragma unroll
            for (int mf = 0; mf < 2; mf++)
#pragma unroll
                for (int nf = 0; nf < NF; nf++)
                    MMA_BF16(acc[mf][nf], ah[mf], bh[nf]);
        }
    };

    if (NS == 2) {
        // K == 64 fast path (kT == 2): both tiles issued upfront, full overlap.
        issue(0, 0);
        issue(1, 32);
        CP_WAIT1();
        __syncthreads();
        compute(0);
        CP_WAIT0();
        __syncthreads();
        compute(1);
    } else {
        const int kT = K / 32;
        int issued = 0;
        for (; issued < NS - 1 && issued < kT; issued++) issue(issued, issued * 32);

        for (int i = 0; i < kT; i++) {
            CP_WAIT1();
            __syncthreads();
            compute(i % NS);
            if (issued < kT) { issue(issued % NS, issued * 32); issued++; }
            else             { CP_COMMIT(); }
        }
    }

    // epilogue
    const int er = lane >> 2;
    const int ec = (lane & 3) * 2;
#pragma unroll
    for (int mf = 0; mf < 2; mf++) {
#pragma unroll
        for (int nf = 0; nf < NF; nf++) {
            int gm = m0 + wm + mf * 16 + er;
            int gn = n0 + wn + nf * 8 + ec;
#pragma unroll
            for (int half = 0; half < 2; half++) {
                int rm = gm + half * 8;
                if (rm >= M) continue;
                float v0 = acc[mf][nf][half * 2 + 0];
                float v1 = acc[mf][nf][half * 2 + 1];
                if (bias) { if (gn < N) v0 += bias[gn]; if (gn + 1 < N) v1 += bias[gn + 1]; }
                if (relu) { v0 = fmaxf(v0, 0.f); v1 = fmaxf(v1, 0.f); }
                if (gn < N) {
                    if (C) {
                        C[(long long)rm * ldc + gn] = v0;
                        if (gn + 1 < N) C[(long long)rm * ldc + gn + 1] = v1;
                    }
                    if (Ch && gn + 1 < N) {
                        bf16 h0, l0, h1, l1;
                        split1(v0, h0, l0); split1(v1, h1, l1);
                        bf162 hp; hp.x = h0; hp.y = h1;
                        bf162 lp; lp.x = l0; lp.y = l1;
                        *reinterpret_cast<bf162*>(&Ch[(long long)rm * ldc + gn]) = hp;
                        *reinterpret_cast<bf162*>(&Cl[(long long)rm * ldc + gn]) = lp;
                    }
                }
            }
        }
    }
}

static inline int smem_bytes(int tb, int tn, int ns) {
    int bs = (tb == 0) ? 32 * (tn + 8) : A_ST32;
    return ns * 2 * (A_ST32 + bs) * 2;
}

static void launch_bf(bool transB,
                      const bf16* Ah, const bf16* Al,
                      const bf16* Bh, const bf16* Bl,
                      float* C, bf16* Ch, bf16* Cl,
                      int M, int N, int K, int lda, int ldb, int ldc,
                      const float* bias, int relu,
                      int batches, int inner,
                      long long oAo, long long oAi,
                      long long oBo, long long oBi,
                      long long oCo, long long oCi,
                      bool tn64 = false)
{
    int tn = tn64 ? 64 : 128;
    dim3 grid((N + tn - 1) / tn, (M + TM - 1) / TM, batches);
    int ns = (K <= 64) ? 2 : 3;
    int sm = smem_bytes(transB ? 1 : 0, tn, ns);
    if (transB) {
        if (K <= 64) {
            // only scores use this (TN=128)
            gemm_bf<1,128,2><<<grid, 512, sm>>>(Ah, Al, Bh, Bl, C, Ch, Cl, M, N, K, lda, ldb, ldc,
                                                bias, relu, inner, oAo, oAi, oBo, oBi, oCo, oCi);
        } else if (tn64) {
            gemm_bf<1,64,3><<<grid, 512, sm>>>(Ah, Al, Bh, Bl, C, Ch, Cl, M, N, K, lda, ldb, ldc,
                                               bias, relu, inner, oAo, oAi, oBo, oBi, oCo, oCi);
        } else {
            gemm_bf<1,128,3><<<grid, 512, sm>>>(Ah, Al, Bh, Bl, C, Ch, Cl, M, N, K, lda, ldb, ldc,
                                                bias, relu, inner, oAo, oAi, oBo, oBi, oCo, oCi);
        }
    } else {
        if (tn64)
            gemm_bf<0,64,3><<<grid, 512, sm>>>(Ah, Al, Bh, Bl, C, Ch, Cl, M, N, K, lda, ldb, ldc,
                                               bias, relu, inner, oAo, oAi, oBo, oBi, oCo, oCi);
        else
            gemm_bf<0,128,3><<<grid, 512, sm>>>(Ah, Al, Bh, Bl, C, Ch, Cl, M, N, K, lda, ldb, ldc,
                                                bias, relu, inner, oAo, oAi, oBo, oBi, oCo, oCi);
    }
}

// ---------------- fused split conversion: all 9 arrays in ONE launch ----------------
#define NSEG_ 9
struct SplitJobs {
    const float4* src[NSEG_];
    bf162* h[NSEG_];
    bf162* l[NSEG_];
    long long cum[NSEG_ + 1];   // cumulative n4 boundaries
};

__global__ void __launch_bounds__(256)
split_all_kernel(SplitJobs J)
{
    long long total = J.cum[NSEG_];
    for (long long g = (long long)blockIdx.x * blockDim.x + threadIdx.x;
         g < total;
         g += (long long)gridDim.x * blockDim.x)
    {
        int s = 0;
#pragma unroll
        for (int k = 1; k < NSEG_; k++) if (g >= J.cum[k]) s = k;
        long long i = g - J.cum[s];
        float4 v = J.src[s][i];
        bf16 h0, l0, h1, l1, h2, l2, h3, l3;
        split1(v.x, h0, l0); split1(v.y, h1, l1);
        split1(v.z, h2, l2); split1(v.w, h3, l3);
        bf162 a; a.x = h0; a.y = h1;
        bf162 b; b.x = h2; b.y = h3;
        J.h[s][2 * i] = a; J.h[s][2 * i + 1] = b;
        a.x = l0; a.y = l1; b.x = l2; b.y = l3;
        J.l[s][2 * i] = a; J.l[s][2 * i + 1] = b;
    }
}

// ---------------- small kernels ----------------
__global__ void detect_seg_kernel(const unsigned char* __restrict__ p)
{
    if (threadIdx.x == 0 && blockIdx.x == 0) {
        bool f32 = false, nonalign = false;
        for (int i = 0; i < 1024; i++) {
            unsigned char c = p[i];
            if ((i & 3) == 3 && c == 0x3F) f32 = true;
            if ((i & 3) != 0 && c == 1)    nonalign = true;
        }
        g_segmode = f32 ? 0 : (nonalign ? 2 : 1);
    }
}

__global__ void build_ctx_kernel(const float* __restrict__ mems_l,
                                 const float* __restrict__ x)
{
    int idx = blockIdx.x * blockDim.x + threadIdx.x;
    if (idx >= B_ * CLEN_ * H_) return;
    int h = idx % H_;
    int j = (idx / H_) % CLEN_;
    int b = idx / (H_ * CLEN_);
    float v = (j < MLEN_) ? mems_l[((long long)b * MLEN_ + j) * H_ + h]
                          : x[((long long)b * QLEN_ + (j - MLEN_)) * H_ + h];
    bf16 hh, ll; split1(v, hh, ll);
    g_cth[idx] = hh; g_ctl[idx] = ll;
}

__global__ void make_qcp_kernel(const float* __restrict__ cb,
                                const float* __restrict__ pb)
{
    int idx = blockIdx.x * blockDim.x + threadIdx.x;
    if (idx >= B_ * QLEN_ * H_) return;
    int nd  = idx % H_;
    float q = g_q[idx];
    bf16 hh, ll;
    split1(q + cb[nd], hh, ll); g_qch[idx] = hh; g_qcl[idx] = ll;
    split1(q + pb[nd], hh, ll); g_qph[idx] = hh; g_qpl[idx] = ll;
}

__global__ void ef_kernel(const float* __restrict__ sb,
                          const float* __restrict__ se_l)
{
    int bi   = blockIdx.x;
    int n    = threadIdx.x >> 5;
    int lane = threadIdx.x & 31;
    const float* qrow = g_q + (long long)bi * H_ + n * D_;
    float s0 = 0.f, s1 = 0.f;
#pragma unroll
    for (int d = lane; d < D_; d += 32) {
        float qv = qrow[d] + sb[n * D_ + d];
        s0 += qv * se_l[n * D_ + d];
        s1 += qv * se_l[NH_ * D_ + n * D_ + d];
    }
#pragma unroll
    for (int o = 16; o > 0; o >>= 1) {
        s0 += __shfl_down_sync(0xFFFFFFFFu, s0, o);
        s1 += __shfl_down_sync(0xFFFFFFFFu, s1, o);
    }
    if (lane == 0) {
        int b = bi / QLEN_;
        int i = bi - b * QLEN_;
        long long ridx = ((long long)(b * NH_ + n) * QLEN_ + i);
        g_ef[ridx]            = s0;
        g_ef[EFSTRIDE + ridx] = s1;
    }
}

__global__ void __launch_bounds__(256)
score_softmax_kernel(const float* __restrict__ mask, const void* __restrict__ seg)
{
    int row = blockIdx.x;
    int i   = row % QLEN_;
    int bn  = row / QLEN_;
    int b   = bn / NH_;
    int tid = threadIdx.x;

    long long rbase = (long long)bn * QLEN_ * CLEN_ + (long long)i * CLEN_;
    const float* ac   = g_sc + rbase;
    const float* bd   = g_bd + (long long)bn * QLEN_ * RLEN_ + (long long)i * RLEN_ + (QLEN_ - i);
    const float* mrow = mask + ((long long)b * QLEN_ + i) * CLEN_;
    long long    sbase = ((long long)b * QLEN_ + i) * (long long)CLEN_;
    float ef0 = g_ef[(long long)bn * QLEN_ + i];
    float ef1 = g_ef[EFSTRIDE + (long long)bn * QLEN_ + i];
    int mode = g_segmode;
    const float rs = 0.125f;

    float vals[4];
    float lmax = -3.0e38f;
#pragma unroll
    for (int u = 0; u < 4; u++) {
        int j = u * 256 + tid;
        bool s;
        if (mode == 2)      s = ((const unsigned char*)seg)[sbase + j] != 0;
        else if (mode == 1) s = ((const int*)seg)[sbase + j] != 0;
        else                s = ((const float*)seg)[sbase + j] != 0.f;
        float ef = s ? ef1 : ef0;
        float sc = (ac[j] + bd[j] + ef) * rs + mrow[j] * (-1e30f);
        vals[u] = sc;
        lmax = fmaxf(lmax, sc);
    }

    __shared__ float red[256];
    red[tid] = lmax;
    __syncthreads();
    for (int o = 128; o > 0; o >>= 1) {
        if (tid < o) red[tid] = fmaxf(red[tid], red[tid + o]);
        __syncthreads();
    }
    float m = red[0];
    __syncthreads();

    float lsum = 0.f;
#pragma unroll
    for (int u = 0; u < 4; u++) {
        vals[u] = __expf(vals[u] - m);
        lsum += vals[u];
    }
    red[tid] = lsum;
    __syncthreads();
    for (int o = 128; o > 0; o >>= 1) {
        if (tid < o) red[tid] += red[tid + o];
        __syncthreads();
    }
    float inv = 1.f / red[0];
#pragma unroll
    for (int u = 0; u < 4; u++) {
        int j = u * 256 + tid;
        bf16 hh, ll; split1(vals[u] * inv, hh, ll);
        g_ph[rbase + j] = hh;
        g_pl[rbase + j] = ll;
    }
}

__global__ void __launch_bounds__(256)
ln_kernel(const float* __restrict__ a, const float* __restrict__ b,
          const float* __restrict__ gamma, const float* __restrict__ beta,
          float* __restrict__ out, bf16* __restrict__ oh, bf16* __restrict__ ol)
{
    int row = blockIdx.x;
    int tid = threadIdx.x;
    const float* pa = a + (long long)row * H_;
    const float* pb = b + (long long)row * H_;

    float v[4];
    float lsum = 0.f;
#pragma unroll
    for (int u = 0; u < 4; u++) {
        int j = u * 256 + tid;
        v[u] = pa[j] + pb[j];
        lsum += v[u];
    }
    __shared__ float red[256];
    red[tid] = lsum;
    __syncthreads();
    for (int o = 128; o > 0; o >>= 1) {
        if (tid < o) red[tid] += red[tid + o];
        __syncthreads();
    }
    float mu = red[0] * (1.0f / H_);
    __syncthreads();

    float lvar = 0.f;
#pragma unroll
    for (int u = 0; u < 4; u++) {
        float d = v[u] - mu;
        lvar += d * d;
    }
    red[tid] = lvar;
    __syncthreads();
    for (int o = 128; o > 0; o >>= 1) {
        if (tid < o) red[tid] += red[tid + o];
        __syncthreads();
    }
    float rstd = rsqrtf(red[0] * (1.0f / H_) + LN_EPS_);
    float* po = out + (long long)row * H_;
#pragma unroll
    for (int u = 0; u < 4; u++) {
        int j = u * 256 + tid;
        float val = (v[u] - mu) * rstd * gamma[j] + beta[j];
        po[j] = val;
        if (oh) {
            bf16 hh, ll; split1(val, hh, ll);
            oh[(long long)row * H_ + j] = hh;
            ol[(long long)row * H_ + j] = ll;
        }
    }
}

// ---------------- host orchestration ----------------
struct Ptrs {
    float *x, *q, *sc, *bd, *ao, *y;
    bf16 *xh,*xl,*cth,*ctl,*peh,*pel,*qch,*qcl,*qph,*qpl,*kh,*kl,*vh,*vl,*rh,*rl,
         *ph,*pl,*ath,*atl,*yh,*yl,*mih,*mil,
         *wqh,*wql,*wkh,*wkl,*wvh,*wvl,*wrh,*wrl,*woh,*wol,*f1h,*f1l,*f2h,*f2l;
    bool init = false;
};

extern "C" void kernel_launch(void* const* d_in, const int* in_sizes, int n_in,
                              void* d_out, int out_size)
{
    (void)in_sizes; (void)n_in; (void)out_size;

    const float* content   = (const float*)d_in[0];
    const float* mask      = (const float*)d_in[1];
    const float* posenc    = (const float*)d_in[2];
    const void*  seg       = d_in[3];
    const float* mems      = (const float*)d_in[4];
    const float* w_q       = (const float*)d_in[5];
    const float* w_k       = (const float*)d_in[6];
    const float* w_v       = (const float*)d_in[7];
    const float* w_r       = (const float*)d_in[8];
    const float* w_o       = (const float*)d_in[9];
    const float* ffn_w1    = (const float*)d_in[10];
    const float* ffn_b1    = (const float*)d_in[11];
    const float* ffn_w2    = (const float*)d_in[12];
    const float* ffn_b2    = (const float*)d_in[13];
    const float* ln1_g     = (const float*)d_in[14];
    const float* ln1_b     = (const float*)d_in[15];
    const float* ln2_g     = (const float*)d_in[16];
    const float* ln2_b     = (const float*)d_in[17];
    const float* cbias     = (const float*)d_in[18];
    const float* pbias     = (const float*)d_in[19];
    const float* sbias     = (const float*)d_in[20];
    const float* segenc    = (const float*)d_in[21];

    static Ptrs S;
    if (!S.init) {
        cudaGetSymbolAddress((void**)&S.x,  g_x);   cudaGetSymbolAddress((void**)&S.q,  g_q);
        cudaGetSymbolAddress((void**)&S.sc, g_sc);  cudaGetSymbolAddress((void**)&S.bd, g_bd);
        cudaGetSymbolAddress((void**)&S.ao, g_ao);  cudaGetSymbolAddress((void**)&S.y,  g_y);
        cudaGetSymbolAddress((void**)&S.xh, g_xh);  cudaGetSymbolAddress((void**)&S.xl, g_xl);
        cudaGetSymbolAddress((void**)&S.cth,g_cth); cudaGetSymbolAddress((void**)&S.ctl,g_ctl);
        cudaGetSymbolAddress((void**)&S.peh,g_peh); cudaGetSymbolAddress((void**)&S.pel,g_pel);
        cudaGetSymbolAddress((void**)&S.qch,g_qch); cudaGetSymbolAddress((void**)&S.qcl,g_qcl);
        cudaGetSymbolAddress((void**)&S.qph,g_qph); cudaGetSymbolAddress((void**)&S.qpl,g_qpl);
        cudaGetSymbolAddress((void**)&S.kh, g_kh);  cudaGetSymbolAddress((void**)&S.kl, g_kl);
        cudaGetSymbolAddress((void**)&S.vh, g_vh);  cudaGetSymbolAddress((void**)&S.vl, g_vl);
        cudaGetSymbolAddress((void**)&S.rh, g_rh);  cudaGetSymbolAddress((void**)&S.rl, g_rl);
        cudaGetSymbolAddress((void**)&S.ph, g_ph);  cudaGetSymbolAddress((void**)&S.pl, g_pl);
        cudaGetSymbolAddress((void**)&S.ath,g_ath); cudaGetSymbolAddress((void**)&S.atl,g_atl);
        cudaGetSymbolAddress((void**)&S.yh, g_yh);  cudaGetSymbolAddress((void**)&S.yl, g_yl);
        cudaGetSymbolAddress((void**)&S.mih,g_mih); cudaGetSymbolAddress((void**)&S.mil,g_mil);
        cudaGetSymbolAddress((void**)&S.wqh,g_wqh); cudaGetSymbolAddress((void**)&S.wql,g_wql);
        cudaGetSymbolAddress((void**)&S.wkh,g_wkh); cudaGetSymbolAddress((void**)&S.wkl,g_wkl);
        cudaGetSymbolAddress((void**)&S.wvh,g_wvh); cudaGetSymbolAddress((void**)&S.wvl,g_wvl);
        cudaGetSymbolAddress((void**)&S.wrh,g_wrh); cudaGetSymbolAddress((void**)&S.wrl,g_wrl);
        cudaGetSymbolAddress((void**)&S.woh,g_woh); cudaGetSymbolAddress((void**)&S.wol,g_wol);
        cudaGetSymbolAddress((void**)&S.f1h,g_f1h); cudaGetSymbolAddress((void**)&S.f1l,g_f1l);
        cudaGetSymbolAddress((void**)&S.f2h,g_f2h); cudaGetSymbolAddress((void**)&S.f2l,g_f2l);
        cudaFuncSetAttribute((const void*)gemm_bf<0,128,3>,
            cudaFuncAttributeMaxDynamicSharedMemorySize, smem_bytes(0,128,3));
        cudaFuncSetAttribute((const void*)gemm_bf<1,128,3>,
            cudaFuncAttributeMaxDynamicSharedMemorySize, smem_bytes(1,128,3));
        cudaFuncSetAttribute((const void*)gemm_bf<0,64,3>,
            cudaFuncAttributeMaxDynamicSharedMemorySize, smem_bytes(0,64,3));
        cudaFuncSetAttribute((const void*)gemm_bf<1,64,3>,
            cudaFuncAttributeMaxDynamicSharedMemorySize, smem_bytes(1,64,3));
        cudaFuncSetAttribute((const void*)gemm_bf<1,128,2>,
            cudaFuncAttributeMaxDynamicSharedMemorySize, smem_bytes(1,128,2));
        S.init = true;
    }

    detect_seg_kernel<<<1, 32>>>((const unsigned char*)seg);

    // fused split of all static arrays (content, posenc, 7 weight tensors)
    {
        SplitJobs J;
        const float* srcs[NSEG_] = {content, posenc, w_q, w_k, w_v, w_r, w_o, ffn_w1, ffn_w2};
        bf16* hs[NSEG_] = {S.xh, S.peh, S.wqh, S.wkh, S.wvh, S.wrh, S.woh, S.f1h, S.f2h};
        bf16* ls[NSEG_] = {S.xl, S.pel, S.wql, S.wkl, S.wvl, S.wrl, S.wol, S.f1l, S.f2l};
        long long ns[NSEG_] = {
            (long long)B_*QLEN_*H_, (long long)B_*RLEN_*H_,
            (long long)L_*H_*H_, (long long)L_*H_*H_, (long long)L_*H_*H_,
            (long long)L_*H_*H_, (long long)L_*H_*H_,
            (long long)L_*H_*F_, (long long)L_*F_*H_};
        long long c = 0;
        for (int s = 0; s < NSEG_; s++) {
            J.src[s] = (const float4*)srcs[s];
            J.h[s]   = (bf162*)hs[s];
            J.l[s]   = (bf162*)ls[s];
            J.cum[s] = c;
            c += ns[s] / 4;
        }
        J.cum[NSEG_] = c;
        int blocks = 148 * 16;
        split_all_kernel<<<blocks, 256>>>(J);
    }

    const float* x = content;
    const int rowsQ = B_ * QLEN_;
    const int rowsC = B_ * CLEN_;
    const int rowsR = B_ * RLEN_;

    for (int l = 0; l < L_; l++) {
        long long wofs = (long long)l * H_ * H_;

        {
            int total = B_ * CLEN_ * H_;
            build_ctx_kernel<<<(total + 255) / 256, 256>>>(
                mems + (long long)l * B_ * MLEN_ * H_, x);
        }

        // q proj (TN=64 -> 128 CTAs)
        launch_bf(false, S.xh, S.xl, S.wqh + wofs, S.wql + wofs,
                  S.q, nullptr, nullptr, rowsQ, H_, H_, H_, H_, H_,
                  nullptr, 0, 1, 1, 0,0,0,0,0,0, /*tn64=*/true);
        launch_bf(false, S.cth, S.ctl, S.wkh + wofs, S.wkl + wofs,
                  nullptr, S.kh, S.kl, rowsC, H_, H_, H_, H_, H_,
                  nullptr, 0, 1, 1, 0,0,0,0,0,0);
        launch_bf(false, S.cth, S.ctl, S.wvh + wofs, S.wvl + wofs,
                  nullptr, S.vh, S.vl, rowsC, H_, H_, H_, H_, H_,
                  nullptr, 0, 1, 1, 0,0,0,0,0,0);
        launch_bf(false, S.peh, S.pel, S.wrh + wofs, S.wrl + wofs,
                  nullptr, S.rh, S.rl, rowsR, H_, H_, H_, H_, H_,
                  nullptr, 0, 1, 1, 0,0,0,0,0,0);

        {
            int total = B_ * QLEN_ * H_;
            make_qcp_kernel<<<(total + 255) / 256, 256>>>(cbias, pbias);
        }
        ef_kernel<<<B_ * QLEN_, 512>>>(sbias, segenc + (long long)l * 2 * NH_ * D_);

        // ac: K=64 -> NS=2 variant, 2 CTAs/SM co-resident
        launch_bf(true, S.qch, S.qcl, S.kh, S.kl,
                  S.sc, nullptr, nullptr,
                  QLEN_, CLEN_, D_, H_, H_, CLEN_,
                  nullptr, 0, B_ * NH_, NH_,
                  (long long)QLEN_ * H_, D_,
                  (long long)CLEN_ * H_, D_,
                  (long long)NH_ * QLEN_ * CLEN_, (long long)QLEN_ * CLEN_);

        // bd: K=64 -> NS=2 variant
        launch_bf(true, S.qph, S.qpl, S.rh, S.rl,
                  S.bd, nullptr, nullptr,
                  QLEN_, RLEN_, D_, H_, H_, RLEN_,
                  nullptr, 0, B_ * NH_, NH_,
                  (long long)QLEN_ * H_, D_,
                  (long long)RLEN_ * H_, D_,
                  (long long)NH_ * QLEN_ * RLEN_, (long long)QLEN_ * RLEN_);

        score_softmax_kernel<<<B_ * NH_ * QLEN_, 256>>>(mask, seg);

        launch_bf(false, S.ph, S.pl, S.vh, S.vl,
                  nullptr, S.ath, S.atl,
                  QLEN_, D_, CLEN_, CLEN_, H_, H_,
                  nullptr, 0, B_ * NH_, NH_,
                  (long long)NH_ * QLEN_ * CLEN_, (long long)QLEN_ * CLEN_,
                  (long long)CLEN_ * H_, D_,
                  (long long)QLEN_ * H_, D_,
                  /*tn64=*/true);

        // out proj (TN=64 -> 128 CTAs)
        launch_bf(true, S.ath, S.atl, S.woh + wofs, S.wol + wofs,
                  S.ao, nullptr, nullptr, rowsQ, H_, H_, H_, H_, H_,
                  nullptr, 0, 1, 1, 0,0,0,0,0,0, /*tn64=*/true);

        ln_kernel<<<rowsQ, 256>>>(S.ao, x, ln1_g + l * H_, ln1_b + l * H_,
                                  S.y, S.yh, S.yl);

        launch_bf(false, S.yh, S.yl, S.f1h + (long long)l * H_ * F_, S.f1l + (long long)l * H_ * F_,
                  nullptr, S.mih, S.mil, rowsQ, F_, H_, H_, F_, F_,
                  ffn_b1 + (long long)l * F_, 1, 1, 1, 0,0,0,0,0,0);
        // ffn2 (TN=64 -> 128 CTAs)
        launch_bf(false, S.mih, S.mil, S.f2h + (long long)l * F_ * H_, S.f2l + (long long)l * F_ * H_,
                  S.ao, nullptr, nullptr, rowsQ, H_, F_, F_, H_, H_,
                  ffn_b2 + (long long)l * H_, 0, 1, 1, 0,0,0,0,0,0, /*tn64=*/true);

        float* xout = (l == L_ - 1) ? (float*)d_out : S.x;
        ln_kernel<<<rowsQ, 256>>>(S.ao, S.y, ln2_g + l * H_, ln2_b + l * H_,
                                  xout, S.xh, S.xl);

        x = S.x;
    }
}